// round 12
// baseline (speedup 1.0000x reference)
#include <cuda_runtime.h>
#include <cuda_fp16.h>
#include <math.h>
#include <stdint.h>

#define BATCH 4
#define SEQ   4096
#define DIM   1024
#define MTOT  (BATCH*SEQ)
#define AP    128

// ---------------- scratch (device globals: allowed) ----------------
__device__ __half g_x16[(size_t)MTOT*DIM];
__device__ __half g_q16[(size_t)MTOT*DIM];
__device__ __half g_k16[(size_t)MTOT*DIM];
__device__ __half g_v16[(size_t)MTOT*DIM];
__device__ __half g_a16[(size_t)MTOT*DIM];    // attn out
__device__ __half g_y16[(size_t)MTOT*DIM];    // ln1 out
__device__ __half g_c16[(size_t)MTOT*DIM];    // Wo out
__device__ __half g_h16[(size_t)MTOT*DIM];    // k1 out
__device__ __half g_wq16[DIM*DIM], g_wk16[DIM*DIM], g_wv16[DIM*DIM];
__device__ __half g_wo16[DIM*DIM], g_w116[DIM*DIM];

// =================== PTX helpers ===================
__device__ __forceinline__ uint32_t s2u(const void* p) {
    uint32_t a;
    asm("{ .reg .u64 t; cvta.to.shared.u64 t, %1; cvt.u32.u64 %0, t; }" : "=r"(a) : "l"(p));
    return a;
}
__device__ __forceinline__ void cp16(uint32_t s, const void* g) {
    asm volatile("cp.async.cg.shared.global [%0], [%1], 16;" :: "r"(s), "l"(g));
}
#define CP_COMMIT() asm volatile("cp.async.commit_group;" ::: "memory")
#define CP_WAIT1()  asm volatile("cp.async.wait_group 1;" ::: "memory")
#define CP_WAIT0()  asm volatile("cp.async.wait_group 0;" ::: "memory")

__device__ __forceinline__ void mma16(float* c, uint32_t a0, uint32_t a1, uint32_t a2,
                                      uint32_t a3, uint32_t b0, uint32_t b1) {
    asm volatile(
        "mma.sync.aligned.m16n8k16.row.col.f32.f16.f16.f32 "
        "{%0,%1,%2,%3}, {%4,%5,%6,%7}, {%8,%9}, {%0,%1,%2,%3};"
        : "+f"(c[0]), "+f"(c[1]), "+f"(c[2]), "+f"(c[3])
        : "r"(a0), "r"(a1), "r"(a2), "r"(a3), "r"(b0), "r"(b1));
}
__device__ __forceinline__ void ldsm4(uint32_t& r0, uint32_t& r1, uint32_t& r2,
                                      uint32_t& r3, uint32_t addr) {
    asm volatile("ldmatrix.sync.aligned.m8n8.x4.shared.b16 {%0,%1,%2,%3}, [%4];"
                 : "=r"(r0), "=r"(r1), "=r"(r2), "=r"(r3) : "r"(addr));
}
__device__ __forceinline__ void ldsm2(uint32_t& r0, uint32_t& r1, uint32_t addr) {
    asm volatile("ldmatrix.sync.aligned.m8n8.x2.shared.b16 {%0,%1}, [%2];"
                 : "=r"(r0), "=r"(r1) : "r"(addr));
}
__device__ __forceinline__ void ldsm4t(uint32_t& r0, uint32_t& r1, uint32_t& r2,
                                       uint32_t& r3, uint32_t addr) {
    asm volatile("ldmatrix.sync.aligned.m8n8.x4.trans.shared.b16 {%0,%1,%2,%3}, [%4];"
                 : "=r"(r0), "=r"(r1), "=r"(r2), "=r"(r3) : "r"(addr));
}

// =================== fp32 -> fp16 conversion ===================
__global__ __launch_bounds__(256)
void conv16(const float* __restrict__ in, __half* __restrict__ out) {
    const size_t i = ((size_t)blockIdx.x * 256 + threadIdx.x) * 4;
    float4 v = *(const float4*)(in + i);
    __half2 h0 = __floats2half2_rn(v.x, v.y);
    __half2 h1 = __floats2half2_rn(v.z, v.w);
    uint2 u;
    u.x = *(uint32_t*)&h0; u.y = *(uint32_t*)&h1;
    *(uint2*)(out + i) = u;
}

__global__ __launch_bounds__(256)
void conv16w(const float* __restrict__ w0, const float* __restrict__ w1,
             const float* __restrict__ w2, const float* __restrict__ w3,
             const float* __restrict__ w4,
             __half* __restrict__ o0, __half* __restrict__ o1,
             __half* __restrict__ o2, __half* __restrict__ o3,
             __half* __restrict__ o4)
{
    const int wsel = blockIdx.x >> 10;
    const int blk  = blockIdx.x & 1023;
    const float* in; __half* out;
    switch (wsel) {
        case 0: in = w0; out = o0; break;
        case 1: in = w1; out = o1; break;
        case 2: in = w2; out = o2; break;
        case 3: in = w3; out = o3; break;
        default: in = w4; out = o4; break;
    }
    const size_t i = ((size_t)blk * 256 + threadIdx.x) * 4;
    float4 v = *(const float4*)(in + i);
    __half2 h0 = __floats2half2_rn(v.x, v.y);
    __half2 h1 = __floats2half2_rn(v.z, v.w);
    uint2 u;
    u.x = *(uint32_t*)&h0; u.y = *(uint32_t*)&h1;
    *(uint2*)(out + i) = u;
}

// =================== fp16 mma.sync GEMM (4 warps, 64x64 warp tile, 3-stage) ===================
#define HBK 64
#define HPITCH 72
#define HSTG_BYTES (128 * 144)
#define GSTAGES 3
#define GEMM_SMEM (2 * GSTAGES * HSTG_BYTES)    // 110592
#define HNSTAGE (DIM / HBK)                      // 16

__global__ __launch_bounds__(128)
void gemm_h(const __half* __restrict__ A, const __half* __restrict__ Bw,
            const float* __restrict__ bias, __half* __restrict__ C16, int doRelu)
{
    extern __shared__ char smc[];
    const uint32_t As_u = s2u(smc);
    const uint32_t Bs_u = As_u + GSTAGES * HSTG_BYTES;

    const int tid  = threadIdx.x;
    const int warp = tid >> 5, lane = tid & 31;
    const int wm = warp >> 1;              // 0..1 : 64-row slice
    const int wn = warp & 1;               // 0..1 : 64-col slice
    const int gid = lane >> 2;
    const int tig = lane & 3;
    const int bm = blockIdx.y * 128;
    const int bn = blockIdx.x * 128;

    // ldmatrix lane->address components
    const int aRow = (lane & 7) + ((lane >> 3) & 1) * 8;
    const int aCol = (lane >> 4) * 8;
    const int bRow = (lane & 7) + (lane >> 4) * 8;
    const int bCol = ((lane >> 3) & 1) * 8;

    float acc[4][8][4];
#pragma unroll
    for (int i = 0; i < 4; i++)
#pragma unroll
        for (int j = 0; j < 8; j++)
#pragma unroll
            for (int k = 0; k < 4; k++) acc[i][j][k] = 0.f;

#define LOADH(stage, buf)                                                        \
    {                                                                            \
        const int k0 = (stage) * HBK;                                            \
        _Pragma("unroll")                                                        \
        for (int l = 0; l < 8; l++) {                                            \
            int slot = tid + l * 128;                                            \
            int row = slot >> 3, c8 = slot & 7;                                  \
            uint32_t so = (uint32_t)(buf) * HSTG_BYTES + row * 144 + c8 * 16;    \
            cp16(As_u + so, A  + (size_t)(bm + row) * DIM + k0 + c8 * 8);        \
            cp16(Bs_u + so, Bw + (size_t)(bn + row) * DIM + k0 + c8 * 8);        \
        }                                                                        \
        CP_COMMIT();                                                             \
    }

    LOADH(0, 0);
    LOADH(1, 1);

    int buf = 0;
    int nbuf = 2;
#pragma unroll 1
    for (int s = 0; s < HNSTAGE; s++) {
        if (s + 1 < HNSTAGE) { CP_WAIT1(); } else { CP_WAIT0(); }
        __syncthreads();
        if (s + 2 < HNSTAGE) LOADH(s + 2, nbuf);

        const uint32_t Ab_u = As_u + (uint32_t)buf * HSTG_BYTES;
        const uint32_t Bb_u = Bs_u + (uint32_t)buf * HSTG_BYTES;

#pragma unroll
        for (int ks = 0; ks < 4; ks++) {
            const int kb0 = ks * 16;
            uint32_t af[4][4], bf[8][2];
#pragma unroll
            for (int mt = 0; mt < 4; mt++) {
                uint32_t addr = Ab_u +
                    (uint32_t)((wm * 64 + mt * 16 + aRow) * HPITCH + kb0 + aCol) * 2;
                ldsm4(af[mt][0], af[mt][1], af[mt][2], af[mt][3], addr);
            }
#pragma unroll
            for (int p = 0; p < 4; p++) {
                uint32_t addr = Bb_u +
                    (uint32_t)((wn * 64 + p * 16 + bRow) * HPITCH + kb0 + bCol) * 2;
                ldsm4(bf[2*p][0], bf[2*p][1], bf[2*p+1][0], bf[2*p+1][1], addr);
            }
#pragma unroll
            for (int mt = 0; mt < 4; mt++)
#pragma unroll
                for (int nt = 0; nt < 8; nt++)
                    mma16(acc[mt][nt], af[mt][0], af[mt][1], af[mt][2], af[mt][3],
                          bf[nt][0], bf[nt][1]);
        }
        buf  = (buf  == GSTAGES - 1) ? 0 : buf + 1;
        nbuf = (nbuf == GSTAGES - 1) ? 0 : nbuf + 1;
    }

#pragma unroll
    for (int mt = 0; mt < 4; mt++) {
#pragma unroll
        for (int nt = 0; nt < 8; nt++) {
            const int col = bn + wn * 64 + nt * 8 + tig * 2;
            float bx = 0.f, by = 0.f;
            if (bias) { bx = bias[col]; by = bias[col + 1]; }
            const int r0 = bm + wm * 64 + mt * 16 + gid;
            float2 v0 = make_float2(acc[mt][nt][0] + bx, acc[mt][nt][1] + by);
            float2 v1 = make_float2(acc[mt][nt][2] + bx, acc[mt][nt][3] + by);
            if (doRelu) {
                v0.x = fmaxf(v0.x, 0.f); v0.y = fmaxf(v0.y, 0.f);
                v1.x = fmaxf(v1.x, 0.f); v1.y = fmaxf(v1.y, 0.f);
            }
            __half2 h0 = __floats2half2_rn(v0.x, v0.y);
            __half2 h1 = __floats2half2_rn(v1.x, v1.y);
            *(uint32_t*)(C16 + (size_t)r0 * DIM + col)       = *(uint32_t*)&h0;
            *(uint32_t*)(C16 + (size_t)(r0 + 8) * DIM + col) = *(uint32_t*)&h1;
        }
    }
}

// =================== tensor-core banded attention (fp16, ldmatrix, 2 CTA/SM) ===================
#define QB    64
#define KW    320
#define KHALF 160
#define PESTR 328
#define VPITCH 136
#define PS_OFF    0
#define PS_BYTES  (QB * PESTR * 2)
#define AQS_OFF   PS_BYTES
#define AQS_STG   (64 * 144)
#define AKS_OFF   (AQS_OFF + 2 * AQS_STG)
#define AKS_STG   (KHALF * 144)
#define AVS_OFF   AQS_OFF
#define AVS_STG   (32 * VPITCH * 2)
#define ATT_SMEM_BYTES (AKS_OFF + 2 * AKS_STG)  // 106496

__global__ __launch_bounds__(256, 2)
void attn_tc(const __half* __restrict__ Q, const __half* __restrict__ Kk,
             const __half* __restrict__ V, __half* __restrict__ O)
{
    extern __shared__ char smc[];
    __half* Ph = (__half*)(smc + PS_OFF);
    const uint32_t smb = s2u(smc);

    const int tid = threadIdx.x;
    const int warp = tid >> 5, lane = tid & 31;
    const int wm = warp >> 2;
    const int wn = warp & 3;
    const int gid = lane >> 2;
    const int tig = lane & 3;
    const int qb = blockIdx.x;
    const int b  = blockIdx.y;
    const int s0 = qb * QB;
    const int ks0 = s0 - AP;
    const size_t brow = (size_t)b * SEQ;
    const float scale = 0.03125f;
    const __half HNEG = __float2half(-60000.f);

    const int aRow = (lane & 7) + ((lane >> 3) & 1) * 8;
    const int aCol = (lane >> 4) * 8;
    const int bRow = (lane & 7) + (lane >> 4) * 8;
    const int bCol = ((lane >> 3) & 1) * 8;
    const int b2Row = (lane & 7);
    const int b2Col = ((lane >> 3) & 1) * 8;

    // ---------- phase 1: scores in two 160-key passes ----------
#define LOAD_QK(stage, buf, nbase)                                                  \
    {                                                                               \
        const int k0 = (stage) * HBK;                                               \
        _Pragma("unroll")                                                           \
        for (int l = 0; l < 2; l++) {                                               \
            int slot = tid + l * 256;                                               \
            int row = slot >> 3, c8 = slot & 7;                                     \
            cp16(smb + AQS_OFF + (buf) * AQS_STG + row * 144 + c8 * 16,             \
                 Q + (brow + s0 + row) * DIM + k0 + c8 * 8);                        \
        }                                                                           \
        _Pragma("unroll")                                                           \
        for (int l = 0; l < 5; l++) {                                               \
            int slot = tid + l * 256;                                               \
            int row = slot >> 3, c8 = slot & 7;                                     \
            int kr = ks0 + (nbase) + row;                                           \
            kr = kr < 0 ? 0 : (kr > SEQ - 1 ? SEQ - 1 : kr);                        \
            cp16(smb + AKS_OFF + (buf) * AKS_STG + row * 144 + c8 * 16,             \
                 Kk + (brow + kr) * DIM + k0 + c8 * 8);                             \
        }                                                                           \
        CP_COMMIT();                                                                \
    }

#pragma unroll 1
    for (int hf = 0; hf < 2; hf++) {
        const int nbase = hf * KHALF;
        float acc[2][5][4];
#pragma unroll
        for (int i = 0; i < 2; i++)
#pragma unroll
            for (int j = 0; j < 5; j++)
#pragma unroll
                for (int k = 0; k < 4; k++) acc[i][j][k] = 0.f;

        LOAD_QK(0, 0, nbase);
        LOAD_QK(1, 1, nbase);

#pragma unroll 1
        for (int s = 0; s < HNSTAGE; s++) {
            const int buf = s & 1;
            if (s + 1 < HNSTAGE) { CP_WAIT1(); } else { CP_WAIT0(); }
            __syncthreads();
            const uint32_t Qb_u = smb + AQS_OFF + (uint32_t)buf * AQS_STG;
            const uint32_t Kb_u = smb + AKS_OFF + (uint32_t)buf * AKS_STG;
#pragma unroll
            for (int ks = 0; ks < 4; ks++) {
                const int kb0 = ks * 16;
                uint32_t af[2][4], bf[5][2];
#pragma unroll
                for (int mt = 0; mt < 2; mt++) {
                    uint32_t addr = Qb_u +
                        (uint32_t)((wm * 32 + mt * 16 + aRow) * HPITCH + kb0 + aCol) * 2;
                    ldsm4(af[mt][0], af[mt][1], af[mt][2], af[mt][3], addr);
                }
#pragma unroll
                for (int p = 0; p < 2; p++) {
                    uint32_t addr = Kb_u +
                        (uint32_t)((wn * 40 + p * 16 + bRow) * HPITCH + kb0 + bCol) * 2;
                    ldsm4(bf[2*p][0], bf[2*p][1], bf[2*p+1][0], bf[2*p+1][1], addr);
                }
                {
                    uint32_t addr = Kb_u +
                        (uint32_t)((wn * 40 + 32 + b2Row) * HPITCH + kb0 + b2Col) * 2;
                    ldsm2(bf[4][0], bf[4][1], addr);
                }
#pragma unroll
                for (int nt = 0; nt < 5; nt++) {
                    mma16(acc[0][nt], af[0][0], af[0][1], af[0][2], af[0][3],
                          bf[nt][0], bf[nt][1]);
                    mma16(acc[1][nt], af[1][0], af[1][1], af[1][2], af[1][3],
                          bf[nt][0], bf[nt][1]);
                }
            }
            __syncthreads();
            if (s + 2 < HNSTAGE) LOAD_QK(s + 2, buf, nbase);
        }

#pragma unroll
        for (int mt = 0; mt < 2; mt++) {
            const int m0 = wm * 32 + mt * 16 + gid;
#pragma unroll
            for (int nt = 0; nt < 5; nt++) {
                const int n0 = nbase + wn * 40 + nt * 8 + tig * 2;
#pragma unroll
                for (int eh = 0; eh < 2; eh++) {
                    const int m = m0 + eh * 8;
                    const int s = s0 + m;
                    __half hv[2];
#pragma unroll
                    for (int e = 0; e < 2; e++) {
                        const int n = n0 + e;
                        const int t = ks0 + n;
                        bool valid = (t >= 0) && (t < SEQ) && (t != s) &&
                                     (t >= s - AP) && (t <= s + AP);
                        hv[e] = valid ? __float2half(acc[mt][nt][eh * 2 + e] * scale)
                                      : HNEG;
                    }
                    *(uint32_t*)&Ph[m * PESTR + n0] = *(uint32_t*)hv;
                }
            }
        }
        __syncthreads();
    }

    // ---------- phase 2: softmax, P fp16 in place ----------
    {
        for (int rr = 0; rr < 8; rr++) {
            const int m = warp * 8 + rr;
            float pv[10];
            float mx = -1e30f;
#pragma unroll
            for (int l = 0; l < 10; l++) {
                pv[l] = __half2float(Ph[m * PESTR + lane + l * 32]);
                mx = fmaxf(mx, pv[l]);
            }
#pragma unroll
            for (int o = 16; o; o >>= 1) mx = fmaxf(mx, __shfl_xor_sync(0xffffffffu, mx, o));
            float ssum = 0.f;
#pragma unroll
            for (int l = 0; l < 10; l++) {
                float p = __expf(pv[l] - mx);
                pv[l] = p;
                ssum += p;
            }
#pragma unroll
            for (int o = 16; o; o >>= 1) ssum += __shfl_xor_sync(0xffffffffu, ssum, o);
            float inv = 1.f / ssum;
#pragma unroll
            for (int l = 0; l < 10; l++)
                Ph[m * PESTR + lane + l * 32] = __float2half(pv[l] * inv);
        }
    }
    __syncthreads();

    // ---------- phase 3: O = P @ V (fp16, ldmatrix both operands) ----------
#define LOAD_V16(tstage, buf, d0v)                                                  \
    {                                                                               \
        const int t0 = (tstage) * 32;                                               \
        _Pragma("unroll")                                                           \
        for (int l = 0; l < 2; l++) {                                               \
            int slot = tid + l * 256;                                               \
            int trow = slot >> 4, c = slot & 15;                                    \
            int tr = ks0 + t0 + trow;                                               \
            tr = tr < 0 ? 0 : (tr > SEQ - 1 ? SEQ - 1 : tr);                        \
            cp16(smb + AVS_OFF + (buf) * AVS_STG + trow * (VPITCH * 2) + c * 16,    \
                 V + (brow + tr) * DIM + (d0v) + c * 8);                            \
        }                                                                           \
        CP_COMMIT();                                                                \
    }

    const int lj   = lane >> 3;
    const int lrow = lane & 7;
    const int t_add = (lj & 1) * 8 + lrow;
    const int d_add = (lj >> 1) * 8;

#pragma unroll 1
    for (int nc = 0; nc < 8; nc++) {
        const int d0 = nc * 128;
        float acc[2][4][4];
#pragma unroll
        for (int i = 0; i < 2; i++)
#pragma unroll
            for (int j = 0; j < 4; j++)
#pragma unroll
                for (int k = 0; k < 4; k++) acc[i][j][k] = 0.f;

        LOAD_V16(0, 0, d0);
        LOAD_V16(1, 1, d0);

#pragma unroll 1
        for (int s = 0; s < 10; s++) {
            const int buf = s & 1;
            if (s + 1 < 10) { CP_WAIT1(); } else { CP_WAIT0(); }
            __syncthreads();
            const uint32_t Vb = smb + AVS_OFF + buf * AVS_STG;
#pragma unroll
            for (int ks = 0; ks < 2; ks++) {
                const int tg = s * 32 + ks * 16;
                uint32_t af[2][4];
#pragma unroll
                for (int mt = 0; mt < 2; mt++) {
                    uint32_t addr = smb +
                        (uint32_t)((wm * 32 + mt * 16 + aRow) * PESTR + tg + aCol) * 2;
                    ldsm4(af[mt][0], af[mt][1], af[mt][2], af[mt][3], addr);
                }
#pragma unroll
                for (int np = 0; np < 2; np++) {
                    const uint32_t addr = Vb +
                        (uint32_t)(ks * 16 + t_add) * (VPITCH * 2) +
                        (uint32_t)(wn * 32 + np * 16 + d_add) * 2;
                    uint32_t r0, r1, r2, r3;
                    ldsm4t(r0, r1, r2, r3, addr);
                    mma16(acc[0][np * 2 + 0], af[0][0], af[0][1], af[0][2], af[0][3], r0, r1);
                    mma16(acc[1][np * 2 + 0], af[1][0], af[1][1], af[1][2], af[1][3], r0, r1);
                    mma16(acc[0][np * 2 + 1], af[0][0], af[0][1], af[0][2], af[0][3], r2, r3);
                    mma16(acc[1][np * 2 + 1], af[1][0], af[1][1], af[1][2], af[1][3], r2, r3);
                }
            }
            __syncthreads();
            if (s + 2 < 10) LOAD_V16(s + 2, buf, d0);
        }

#pragma unroll
        for (int mt = 0; mt < 2; mt++) {
            const int m0 = wm * 32 + mt * 16 + gid;
#pragma unroll
            for (int nt = 0; nt < 4; nt++) {
                const int col = d0 + wn * 32 + nt * 8 + tig * 2;
                __half2 h0 = __floats2half2_rn(acc[mt][nt][0], acc[mt][nt][1]);
                __half2 h1 = __floats2half2_rn(acc[mt][nt][2], acc[mt][nt][3]);
                *(uint32_t*)(O + (brow + s0 + m0) * DIM + col)     = *(uint32_t*)&h0;
                *(uint32_t*)(O + (brow + s0 + m0 + 8) * DIM + col) = *(uint32_t*)&h1;
            }
        }
    }
}

// ---------------- residual + LayerNorm (fp16 X, fp32 residual, fp16 out) ----------------
__global__ __launch_bounds__(256)
void ln_kernel(const __half* __restrict__ X, const float* __restrict__ R,
               const float* __restrict__ g, const float* __restrict__ bta,
               __half* __restrict__ Yh)
{
    const int r = blockIdx.x, tid = threadIdx.x;
    const size_t base = (size_t)r * DIM;
    uint2 xu = *(const uint2*)(X + base + tid * 4);
    __half2 xh0 = *(__half2*)&xu.x, xh1 = *(__half2*)&xu.y;
    float2 f0 = __half22float2(xh0), f1 = __half22float2(xh1);
    float4 v = make_float4(f0.x, f0.y, f1.x, f1.y);
    float4 rv = *(const float4*)(R + base + tid * 4);
    v.x += rv.x; v.y += rv.y; v.z += rv.z; v.w += rv.w;

    __shared__ float red[8];
    __shared__ float s_mu, s_inv;
    const int w = tid >> 5, lane = tid & 31;

    float s = v.x + v.y + v.z + v.w;
#pragma unroll
    for (int o = 16; o; o >>= 1) s += __shfl_xor_sync(0xffffffffu, s, o);
    if (lane == 0) red[w] = s;
    __syncthreads();
    if (tid == 0) {
        float t = 0.f;
#pragma unroll
        for (int i = 0; i < 8; i++) t += red[i];
        s_mu = t * (1.f / DIM);
    }
    __syncthreads();
    float mu = s_mu;

    float dx = v.x - mu, dy = v.y - mu, dz = v.z - mu, dw = v.w - mu;
    float ss = dx*dx + dy*dy + dz*dz + dw*dw;
#pragma unroll
    for (int o = 16; o; o >>= 1) ss += __shfl_xor_sync(0xffffffffu, ss, o);
    if (lane == 0) red[w] = ss;
    __syncthreads();
    if (tid == 0) {
        float t = 0.f;
#pragma unroll
        for (int i = 0; i < 8; i++) t += red[i];
        s_inv = rsqrtf(t * (1.f / DIM) + 1e-6f);
    }
    __syncthreads();
    float inv = s_inv;

    float4 gg = *(const float4*)(g + tid * 4);
    float4 bb = *(const float4*)(bta + tid * 4);
    float ox = dx * inv * gg.x + bb.x;
    float oy = dy * inv * gg.y + bb.y;
    float oz = dz * inv * gg.z + bb.z;
    float ow = dw * inv * gg.w + bb.w;
    __half2 h0 = __floats2half2_rn(ox, oy);
    __half2 h1 = __floats2half2_rn(oz, ow);
    uint2 u; u.x = *(uint32_t*)&h0; u.y = *(uint32_t*)&h1;
    *(uint2*)(Yh + base + tid * 4) = u;
}

// ---------------- fused LayerNorm + head (fp16 X) ----------------
__global__ __launch_bounds__(256)
void ln_head(const __half* __restrict__ X,
             const float* __restrict__ g, const float* __restrict__ bta,
             const float* __restrict__ w, const float* __restrict__ bias,
             float* __restrict__ out)
{
    const int r = blockIdx.x, tid = threadIdx.x;
    const size_t base = (size_t)r * DIM;
    uint2 xu = *(const uint2*)(X + base + tid * 4);
    __half2 xh0 = *(__half2*)&xu.x, xh1 = *(__half2*)&xu.y;
    float2 f0 = __half22float2(xh0), f1 = __half22float2(xh1);
    float4 v = make_float4(f0.x, f0.y, f1.x, f1.y);

    __shared__ float red[8];
    __shared__ float s_mu, s_inv;
    const int wr = tid >> 5, lane = tid & 31;

    float s = v.x + v.y + v.z + v.w;
#pragma unroll
    for (int o = 16; o; o >>= 1) s += __shfl_xor_sync(0xffffffffu, s, o);
    if (lane == 0) red[wr] = s;
    __syncthreads();
    if (tid == 0) {
        float t = 0.f;
#pragma unroll
        for (int i = 0; i < 8; i++) t += red[i];
        s_mu = t * (1.f / DIM);
    }
    __syncthreads();
    float mu = s_mu;

    float dx = v.x - mu, dy = v.y - mu, dz = v.z - mu, dw = v.w - mu;
    float ss = dx*dx + dy*dy + dz*dz + dw*dw;
#pragma unroll
    for (int o = 16; o; o >>= 1) ss += __shfl_xor_sync(0xffffffffu, ss, o);
    if (lane == 0) red[wr] = ss;
    __syncthreads();
    if (tid == 0) {
        float t = 0.f;
#pragma unroll
        for (int i = 0; i < 8; i++) t += red[i];
        s_inv = rsqrtf(t * (1.f / DIM) + 1e-6f);
    }
    __syncthreads();
    float inv = s_inv;

    float4 gg = *(const float4*)(g + tid * 4);
    float4 bb = *(const float4*)(bta + tid * 4);
    float4 ww = *(const float4*)(w + tid * 4);
    float dot = (dx * inv * gg.x + bb.x) * ww.x
              + (dy * inv * gg.y + bb.y) * ww.y
              + (dz * inv * gg.z + bb.z) * ww.z
              + (dw * inv * gg.w + bb.w) * ww.w;
#pragma unroll
    for (int o = 16; o; o >>= 1) dot += __shfl_xor_sync(0xffffffffu, dot, o);
    if (lane == 0) red[wr] = dot;
    __syncthreads();
    if (tid == 0) {
        float t = 0.f;
#pragma unroll
        for (int i = 0; i < 8; i++) t += red[i];
        t += bias[0];
        out[r] = 1.f / (1.f + expf(-t));
    }
}

// ---------------- launch ----------------
extern "C" void kernel_launch(void* const* d_in, const int* in_sizes, int n_in,
                              void* d_out, int out_size)
{
    const float* x   = (const float*)d_in[0];
    const float* Wq  = (const float*)d_in[1];
    const float* Wk  = (const float*)d_in[2];
    const float* Wv  = (const float*)d_in[3];
    const float* Wo  = (const float*)d_in[4];
    const float* k1w = (const float*)d_in[5];
    const float* k1b = (const float*)d_in[6];
    const float* k2w = (const float*)d_in[7];
    const float* k2b = (const float*)d_in[8];
    const float* lng = (const float*)d_in[9];
    const float* lnb = (const float*)d_in[10];
    float* out = (float*)d_out;

    __half *x16, *q16, *k16, *v16, *a16, *y16, *c16, *h16;
    __half *wq16, *wk16, *wv16, *wo16, *w116;
    cudaGetSymbolAddress((void**)&x16, g_x16);
    cudaGetSymbolAddress((void**)&q16, g_q16);
    cudaGetSymbolAddress((void**)&k16, g_k16);
    cudaGetSymbolAddress((void**)&v16, g_v16);
    cudaGetSymbolAddress((void**)&a16, g_a16);
    cudaGetSymbolAddress((void**)&y16, g_y16);
    cudaGetSymbolAddress((void**)&c16, g_c16);
    cudaGetSymbolAddress((void**)&h16, g_h16);
    cudaGetSymbolAddress((void**)&wq16, g_wq16);
    cudaGetSymbolAddress((void**)&wk16, g_wk16);
    cudaGetSymbolAddress((void**)&wv16, g_wv16);
    cudaGetSymbolAddress((void**)&wo16, g_wo16);
    cudaGetSymbolAddress((void**)&w116, g_w116);

    cudaFuncSetAttribute(attn_tc, cudaFuncAttributeMaxDynamicSharedMemorySize,
                         ATT_SMEM_BYTES);
    cudaFuncSetAttribute(gemm_h, cudaFuncAttributeMaxDynamicSharedMemorySize,
                         GEMM_SMEM);

    conv16<<<(MTOT * DIM) / 1024, 256>>>(x, x16);
    conv16w<<<5 * 1024, 256>>>(Wq, Wk, Wv, Wo, k1w,
                               wq16, wk16, wv16, wo16, w116);

    dim3 gg(DIM / 128, MTOT / 128);   // (8, 128)

    gemm_h<<<gg, 128, GEMM_SMEM>>>(x16, wq16, nullptr, q16, 0);
    gemm_h<<<gg, 128, GEMM_SMEM>>>(x16, wk16, nullptr, k16, 0);
    gemm_h<<<gg, 128, GEMM_SMEM>>>(x16, wv16, nullptr, v16, 0);

    attn_tc<<<dim3(SEQ / QB, BATCH), 256, ATT_SMEM_BYTES>>>(q16, k16, v16, a16);

    gemm_h<<<gg, 128, GEMM_SMEM>>>(a16, wo16, nullptr, c16, 0);
    ln_kernel<<<MTOT, 256>>>(c16, x, lng, lnb, y16);
    gemm_h<<<gg, 128, GEMM_SMEM>>>(y16, w116, k1b, h16, 1);
    ln_head<<<MTOT, 256>>>(h16, lng, lnb, k2w, k2b, out);
}

// round 13
// speedup vs baseline: 1.0865x; 1.0865x over previous
#include <cuda_runtime.h>
#include <cuda_fp16.h>
#include <math.h>
#include <stdint.h>

#define BATCH 4
#define SEQ   4096
#define DIM   1024
#define MTOT  (BATCH*SEQ)
#define AP    128

// ---------------- scratch (device globals: allowed) ----------------
__device__ __half g_x16[(size_t)MTOT*DIM];
__device__ __half g_q16[(size_t)MTOT*DIM];
__device__ __half g_k16[(size_t)MTOT*DIM];
__device__ __half g_v16[(size_t)MTOT*DIM];
__device__ __half g_a16[(size_t)MTOT*DIM];    // attn out
__device__ __half g_y16[(size_t)MTOT*DIM];    // ln1 out
__device__ __half g_c16[(size_t)MTOT*DIM];    // Wo out
__device__ __half g_h16[(size_t)MTOT*DIM];    // k1 out
__device__ __half g_wq16[DIM*DIM], g_wk16[DIM*DIM], g_wv16[DIM*DIM];
__device__ __half g_wo16[DIM*DIM], g_w116[DIM*DIM];

// =================== PTX helpers ===================
__device__ __forceinline__ uint32_t s2u(const void* p) {
    uint32_t a;
    asm("{ .reg .u64 t; cvta.to.shared.u64 t, %1; cvt.u32.u64 %0, t; }" : "=r"(a) : "l"(p));
    return a;
}
__device__ __forceinline__ void cp16(uint32_t s, const void* g) {
    asm volatile("cp.async.cg.shared.global [%0], [%1], 16;" :: "r"(s), "l"(g));
}
#define CP_COMMIT() asm volatile("cp.async.commit_group;" ::: "memory")
#define CP_WAIT1()  asm volatile("cp.async.wait_group 1;" ::: "memory")
#define CP_WAIT0()  asm volatile("cp.async.wait_group 0;" ::: "memory")

__device__ __forceinline__ void mma16(float* c, uint32_t a0, uint32_t a1, uint32_t a2,
                                      uint32_t a3, uint32_t b0, uint32_t b1) {
    asm volatile(
        "mma.sync.aligned.m16n8k16.row.col.f32.f16.f16.f32 "
        "{%0,%1,%2,%3}, {%4,%5,%6,%7}, {%8,%9}, {%0,%1,%2,%3};"
        : "+f"(c[0]), "+f"(c[1]), "+f"(c[2]), "+f"(c[3])
        : "r"(a0), "r"(a1), "r"(a2), "r"(a3), "r"(b0), "r"(b1));
}
__device__ __forceinline__ void ldsm4(uint32_t& r0, uint32_t& r1, uint32_t& r2,
                                      uint32_t& r3, uint32_t addr) {
    asm volatile("ldmatrix.sync.aligned.m8n8.x4.shared.b16 {%0,%1,%2,%3}, [%4];"
                 : "=r"(r0), "=r"(r1), "=r"(r2), "=r"(r3) : "r"(addr));
}
__device__ __forceinline__ void ldsm2(uint32_t& r0, uint32_t& r1, uint32_t addr) {
    asm volatile("ldmatrix.sync.aligned.m8n8.x2.shared.b16 {%0,%1}, [%2];"
                 : "=r"(r0), "=r"(r1) : "r"(addr));
}
__device__ __forceinline__ void ldsm4t(uint32_t& r0, uint32_t& r1, uint32_t& r2,
                                       uint32_t& r3, uint32_t addr) {
    asm volatile("ldmatrix.sync.aligned.m8n8.x4.trans.shared.b16 {%0,%1,%2,%3}, [%4];"
                 : "=r"(r0), "=r"(r1), "=r"(r2), "=r"(r3) : "r"(addr));
}

// =================== fp32 -> fp16 conversion ===================
__global__ __launch_bounds__(256)
void conv16(const float* __restrict__ in, __half* __restrict__ out) {
    const size_t i = ((size_t)blockIdx.x * 256 + threadIdx.x) * 4;
    float4 v = *(const float4*)(in + i);
    __half2 h0 = __floats2half2_rn(v.x, v.y);
    __half2 h1 = __floats2half2_rn(v.z, v.w);
    uint2 u;
    u.x = *(uint32_t*)&h0; u.y = *(uint32_t*)&h1;
    *(uint2*)(out + i) = u;
}

__global__ __launch_bounds__(256)
void conv16w(const float* __restrict__ w0, const float* __restrict__ w1,
             const float* __restrict__ w2, const float* __restrict__ w3,
             const float* __restrict__ w4,
             __half* __restrict__ o0, __half* __restrict__ o1,
             __half* __restrict__ o2, __half* __restrict__ o3,
             __half* __restrict__ o4)
{
    const int wsel = blockIdx.x >> 10;
    const int blk  = blockIdx.x & 1023;
    const float* in; __half* out;
    switch (wsel) {
        case 0: in = w0; out = o0; break;
        case 1: in = w1; out = o1; break;
        case 2: in = w2; out = o2; break;
        case 3: in = w3; out = o3; break;
        default: in = w4; out = o4; break;
    }
    const size_t i = ((size_t)blk * 256 + threadIdx.x) * 4;
    float4 v = *(const float4*)(in + i);
    __half2 h0 = __floats2half2_rn(v.x, v.y);
    __half2 h1 = __floats2half2_rn(v.z, v.w);
    uint2 u;
    u.x = *(uint32_t*)&h0; u.y = *(uint32_t*)&h1;
    *(uint2*)(out + i) = u;
}

// =================== fp16 mma.sync GEMM (8 warps, 64x32 warp tile, 3-stage) ===================
#define HBK 64
#define HPITCH 72
#define HSTG_BYTES (128 * 144)
#define GSTAGES 3
#define GEMM_SMEM (2 * GSTAGES * HSTG_BYTES)    // 110592
#define HNSTAGE (DIM / HBK)                      // 16

// Shared GEMM body: computes C16 = A @ Bw^T (+bias,+relu), 128x128 CTA tile.
__device__ __forceinline__ void gemm_body(
    const __half* __restrict__ A, const __half* __restrict__ Bw,
    const float* __restrict__ bias, __half* __restrict__ C16, int doRelu,
    char* smc, int bm, int bn)
{
    const uint32_t As_u = s2u(smc);
    const uint32_t Bs_u = As_u + GSTAGES * HSTG_BYTES;

    const int tid  = threadIdx.x;
    const int warp = tid >> 5, lane = tid & 31;
    const int wm = warp >> 2;
    const int wn = warp & 3;
    const int gid = lane >> 2;
    const int tig = lane & 3;

    const int aRow = (lane & 7) + ((lane >> 3) & 1) * 8;
    const int aCol = (lane >> 4) * 8;
    const int bRow = (lane & 7) + (lane >> 4) * 8;
    const int bCol = ((lane >> 3) & 1) * 8;

    float acc[4][4][4];
#pragma unroll
    for (int i = 0; i < 4; i++)
#pragma unroll
        for (int j = 0; j < 4; j++)
#pragma unroll
            for (int k = 0; k < 4; k++) acc[i][j][k] = 0.f;

#define LOADH(stage, buf)                                                        \
    {                                                                            \
        const int k0 = (stage) * HBK;                                            \
        _Pragma("unroll")                                                        \
        for (int l = 0; l < 4; l++) {                                            \
            int slot = tid + l * 256;                                            \
            int row = slot >> 3, c8 = slot & 7;                                  \
            uint32_t so = (uint32_t)(buf) * HSTG_BYTES + row * 144 + c8 * 16;    \
            cp16(As_u + so, A  + (size_t)(bm + row) * DIM + k0 + c8 * 8);        \
            cp16(Bs_u + so, Bw + (size_t)(bn + row) * DIM + k0 + c8 * 8);        \
        }                                                                        \
        CP_COMMIT();                                                             \
    }

    LOADH(0, 0);
    LOADH(1, 1);

    int buf = 0;
    int nbuf = 2;
#pragma unroll 1
    for (int s = 0; s < HNSTAGE; s++) {
        if (s + 1 < HNSTAGE) { CP_WAIT1(); } else { CP_WAIT0(); }
        __syncthreads();
        if (s + 2 < HNSTAGE) LOADH(s + 2, nbuf);

        const uint32_t Ab_u = As_u + (uint32_t)buf * HSTG_BYTES;
        const uint32_t Bb_u = Bs_u + (uint32_t)buf * HSTG_BYTES;

#pragma unroll
        for (int ks = 0; ks < 4; ks++) {
            const int kb0 = ks * 16;
            uint32_t af[4][4], bf[4][2];
#pragma unroll
            for (int mt = 0; mt < 4; mt++) {
                uint32_t addr = Ab_u +
                    (uint32_t)((wm * 64 + mt * 16 + aRow) * HPITCH + kb0 + aCol) * 2;
                ldsm4(af[mt][0], af[mt][1], af[mt][2], af[mt][3], addr);
            }
#pragma unroll
            for (int p = 0; p < 2; p++) {
                uint32_t addr = Bb_u +
                    (uint32_t)((wn * 32 + p * 16 + bRow) * HPITCH + kb0 + bCol) * 2;
                ldsm4(bf[2*p][0], bf[2*p][1], bf[2*p+1][0], bf[2*p+1][1], addr);
            }
#pragma unroll
            for (int mt = 0; mt < 4; mt++)
#pragma unroll
                for (int nt = 0; nt < 4; nt++)
                    mma16(acc[mt][nt], af[mt][0], af[mt][1], af[mt][2], af[mt][3],
                          bf[nt][0], bf[nt][1]);
        }
        buf  = (buf  == GSTAGES - 1) ? 0 : buf + 1;
        nbuf = (nbuf == GSTAGES - 1) ? 0 : nbuf + 1;
    }

#pragma unroll
    for (int mt = 0; mt < 4; mt++) {
#pragma unroll
        for (int nt = 0; nt < 4; nt++) {
            const int col = bn + wn * 32 + nt * 8 + tig * 2;
            float bx = 0.f, by = 0.f;
            if (bias) { bx = bias[col]; by = bias[col + 1]; }
            const int r0 = bm + wm * 64 + mt * 16 + gid;
            float2 v0 = make_float2(acc[mt][nt][0] + bx, acc[mt][nt][1] + by);
            float2 v1 = make_float2(acc[mt][nt][2] + bx, acc[mt][nt][3] + by);
            if (doRelu) {
                v0.x = fmaxf(v0.x, 0.f); v0.y = fmaxf(v0.y, 0.f);
                v1.x = fmaxf(v1.x, 0.f); v1.y = fmaxf(v1.y, 0.f);
            }
            __half2 h0 = __floats2half2_rn(v0.x, v0.y);
            __half2 h1 = __floats2half2_rn(v1.x, v1.y);
            *(uint32_t*)(C16 + (size_t)r0 * DIM + col)       = *(uint32_t*)&h0;
            *(uint32_t*)(C16 + (size_t)(r0 + 8) * DIM + col) = *(uint32_t*)&h1;
        }
    }
}

__global__ __launch_bounds__(256)
void gemm_h(const __half* __restrict__ A, const __half* __restrict__ Bw,
            const float* __restrict__ bias, __half* __restrict__ C16, int doRelu)
{
    extern __shared__ char smc[];
    gemm_body(A, Bw, bias, C16, doRelu, smc, blockIdx.y * 128, blockIdx.x * 128);
}

// Fused QKV: gridDim.z selects the weight/output pair (shared A operand).
__global__ __launch_bounds__(256)
void gemm_qkv(const __half* __restrict__ A,
              const __half* __restrict__ W0, const __half* __restrict__ W1,
              const __half* __restrict__ W2,
              __half* __restrict__ C0, __half* __restrict__ C1,
              __half* __restrict__ C2)
{
    extern __shared__ char smc[];
    const __half* Bw; __half* C;
    if (blockIdx.z == 0)      { Bw = W0; C = C0; }
    else if (blockIdx.z == 1) { Bw = W1; C = C1; }
    else                      { Bw = W2; C = C2; }
    gemm_body(A, Bw, nullptr, C, 0, smc, blockIdx.y * 128, blockIdx.x * 128);
}

// =================== tensor-core banded attention (fp16, ldmatrix, 2 CTA/SM) ===================
#define QB    64
#define KW    320
#define KHALF 160
#define PESTR 328
#define VPITCH 136
#define PS_OFF    0
#define PS_BYTES  (QB * PESTR * 2)
#define AQS_OFF   PS_BYTES
#define AQS_STG   (64 * 144)
#define AKS_OFF   (AQS_OFF + 2 * AQS_STG)
#define AKS_STG   (KHALF * 144)
#define AVS_OFF   AQS_OFF
#define AVS_STG   (32 * VPITCH * 2)
#define ATT_SMEM_BYTES (AKS_OFF + 2 * AKS_STG)  // 106496

__global__ __launch_bounds__(256, 2)
void attn_tc(const __half* __restrict__ Q, const __half* __restrict__ Kk,
             const __half* __restrict__ V, __half* __restrict__ O)
{
    extern __shared__ char smc[];
    __half* Ph = (__half*)(smc + PS_OFF);
    const uint32_t smb = s2u(smc);

    const int tid = threadIdx.x;
    const int warp = tid >> 5, lane = tid & 31;
    const int wm = warp >> 2;
    const int wn = warp & 3;
    const int gid = lane >> 2;
    const int tig = lane & 3;
    const int qb = blockIdx.x;
    const int b  = blockIdx.y;
    const int s0 = qb * QB;
    const int ks0 = s0 - AP;
    const size_t brow = (size_t)b * SEQ;
    const float scale = 0.03125f;
    const __half HNEG = __float2half(-60000.f);

    const int aRow = (lane & 7) + ((lane >> 3) & 1) * 8;
    const int aCol = (lane >> 4) * 8;
    const int bRow = (lane & 7) + (lane >> 4) * 8;
    const int bCol = ((lane >> 3) & 1) * 8;
    const int b2Row = (lane & 7);
    const int b2Col = ((lane >> 3) & 1) * 8;

    // ---------- phase 1: scores in two 160-key passes ----------
#define LOAD_QK(stage, buf, nbase)                                                  \
    {                                                                               \
        const int k0 = (stage) * HBK;                                               \
        _Pragma("unroll")                                                           \
        for (int l = 0; l < 2; l++) {                                               \
            int slot = tid + l * 256;                                               \
            int row = slot >> 3, c8 = slot & 7;                                     \
            cp16(smb + AQS_OFF + (buf) * AQS_STG + row * 144 + c8 * 16,             \
                 Q + (brow + s0 + row) * DIM + k0 + c8 * 8);                        \
        }                                                                           \
        _Pragma("unroll")                                                           \
        for (int l = 0; l < 5; l++) {                                               \
            int slot = tid + l * 256;                                               \
            int row = slot >> 3, c8 = slot & 7;                                     \
            int kr = ks0 + (nbase) + row;                                           \
            kr = kr < 0 ? 0 : (kr > SEQ - 1 ? SEQ - 1 : kr);                        \
            cp16(smb + AKS_OFF + (buf) * AKS_STG + row * 144 + c8 * 16,             \
                 Kk + (brow + kr) * DIM + k0 + c8 * 8);                             \
        }                                                                           \
        CP_COMMIT();                                                                \
    }

#pragma unroll 1
    for (int hf = 0; hf < 2; hf++) {
        const int nbase = hf * KHALF;
        float acc[2][5][4];
#pragma unroll
        for (int i = 0; i < 2; i++)
#pragma unroll
            for (int j = 0; j < 5; j++)
#pragma unroll
                for (int k = 0; k < 4; k++) acc[i][j][k] = 0.f;

        LOAD_QK(0, 0, nbase);
        LOAD_QK(1, 1, nbase);

#pragma unroll 1
        for (int s = 0; s < HNSTAGE; s++) {
            const int buf = s & 1;
            if (s + 1 < HNSTAGE) { CP_WAIT1(); } else { CP_WAIT0(); }
            __syncthreads();
            const uint32_t Qb_u = smb + AQS_OFF + (uint32_t)buf * AQS_STG;
            const uint32_t Kb_u = smb + AKS_OFF + (uint32_t)buf * AKS_STG;
#pragma unroll
            for (int ks = 0; ks < 4; ks++) {
                const int kb0 = ks * 16;
                uint32_t af[2][4], bf[5][2];
#pragma unroll
                for (int mt = 0; mt < 2; mt++) {
                    uint32_t addr = Qb_u +
                        (uint32_t)((wm * 32 + mt * 16 + aRow) * HPITCH + kb0 + aCol) * 2;
                    ldsm4(af[mt][0], af[mt][1], af[mt][2], af[mt][3], addr);
                }
#pragma unroll
                for (int p = 0; p < 2; p++) {
                    uint32_t addr = Kb_u +
                        (uint32_t)((wn * 40 + p * 16 + bRow) * HPITCH + kb0 + bCol) * 2;
                    ldsm4(bf[2*p][0], bf[2*p][1], bf[2*p+1][0], bf[2*p+1][1], addr);
                }
                {
                    uint32_t addr = Kb_u +
                        (uint32_t)((wn * 40 + 32 + b2Row) * HPITCH + kb0 + b2Col) * 2;
                    ldsm2(bf[4][0], bf[4][1], addr);
                }
#pragma unroll
                for (int nt = 0; nt < 5; nt++) {
                    mma16(acc[0][nt], af[0][0], af[0][1], af[0][2], af[0][3],
                          bf[nt][0], bf[nt][1]);
                    mma16(acc[1][nt], af[1][0], af[1][1], af[1][2], af[1][3],
                          bf[nt][0], bf[nt][1]);
                }
            }
            __syncthreads();
            if (s + 2 < HNSTAGE) LOAD_QK(s + 2, buf, nbase);
        }

#pragma unroll
        for (int mt = 0; mt < 2; mt++) {
            const int m0 = wm * 32 + mt * 16 + gid;
#pragma unroll
            for (int nt = 0; nt < 5; nt++) {
                const int n0 = nbase + wn * 40 + nt * 8 + tig * 2;
#pragma unroll
                for (int eh = 0; eh < 2; eh++) {
                    const int m = m0 + eh * 8;
                    const int s = s0 + m;
                    __half hv[2];
#pragma unroll
                    for (int e = 0; e < 2; e++) {
                        const int n = n0 + e;
                        const int t = ks0 + n;
                        bool valid = (t >= 0) && (t < SEQ) && (t != s) &&
                                     (t >= s - AP) && (t <= s + AP);
                        hv[e] = valid ? __float2half(acc[mt][nt][eh * 2 + e] * scale)
                                      : HNEG;
                    }
                    *(uint32_t*)&Ph[m * PESTR + n0] = *(uint32_t*)hv;
                }
            }
        }
        __syncthreads();
    }

    // ---------- phase 2: softmax, P fp16 in place ----------
    {
        for (int rr = 0; rr < 8; rr++) {
            const int m = warp * 8 + rr;
            float pv[10];
            float mx = -1e30f;
#pragma unroll
            for (int l = 0; l < 10; l++) {
                pv[l] = __half2float(Ph[m * PESTR + lane + l * 32]);
                mx = fmaxf(mx, pv[l]);
            }
#pragma unroll
            for (int o = 16; o; o >>= 1) mx = fmaxf(mx, __shfl_xor_sync(0xffffffffu, mx, o));
            float ssum = 0.f;
#pragma unroll
            for (int l = 0; l < 10; l++) {
                float p = __expf(pv[l] - mx);
                pv[l] = p;
                ssum += p;
            }
#pragma unroll
            for (int o = 16; o; o >>= 1) ssum += __shfl_xor_sync(0xffffffffu, ssum, o);
            float inv = 1.f / ssum;
#pragma unroll
            for (int l = 0; l < 10; l++)
                Ph[m * PESTR + lane + l * 32] = __float2half(pv[l] * inv);
        }
    }
    __syncthreads();

    // ---------- phase 3: O = P @ V (fp16, ldmatrix both operands) ----------
#define LOAD_V16(tstage, buf, d0v)                                                  \
    {                                                                               \
        const int t0 = (tstage) * 32;                                               \
        _Pragma("unroll")                                                           \
        for (int l = 0; l < 2; l++) {                                               \
            int slot = tid + l * 256;                                               \
            int trow = slot >> 4, c = slot & 15;                                    \
            int tr = ks0 + t0 + trow;                                               \
            tr = tr < 0 ? 0 : (tr > SEQ - 1 ? SEQ - 1 : tr);                        \
            cp16(smb + AVS_OFF + (buf) * AVS_STG + trow * (VPITCH * 2) + c * 16,    \
                 V + (brow + tr) * DIM + (d0v) + c * 8);                            \
        }                                                                           \
        CP_COMMIT();                                                                \
    }

    const int lj   = lane >> 3;
    const int lrow = lane & 7;
    const int t_add = (lj & 1) * 8 + lrow;
    const int d_add = (lj >> 1) * 8;

#pragma unroll 1
    for (int nc = 0; nc < 8; nc++) {
        const int d0 = nc * 128;
        float acc[2][4][4];
#pragma unroll
        for (int i = 0; i < 2; i++)
#pragma unroll
            for (int j = 0; j < 4; j++)
#pragma unroll
                for (int k = 0; k < 4; k++) acc[i][j][k] = 0.f;

        LOAD_V16(0, 0, d0);
        LOAD_V16(1, 1, d0);

#pragma unroll 1
        for (int s = 0; s < 10; s++) {
            const int buf = s & 1;
            if (s + 1 < 10) { CP_WAIT1(); } else { CP_WAIT0(); }
            __syncthreads();
            const uint32_t Vb = smb + AVS_OFF + buf * AVS_STG;
#pragma unroll
            for (int ks = 0; ks < 2; ks++) {
                const int tg = s * 32 + ks * 16;
                uint32_t af[2][4];
#pragma unroll
                for (int mt = 0; mt < 2; mt++) {
                    uint32_t addr = smb +
                        (uint32_t)((wm * 32 + mt * 16 + aRow) * PESTR + tg + aCol) * 2;
                    ldsm4(af[mt][0], af[mt][1], af[mt][2], af[mt][3], addr);
                }
#pragma unroll
                for (int np = 0; np < 2; np++) {
                    const uint32_t addr = Vb +
                        (uint32_t)(ks * 16 + t_add) * (VPITCH * 2) +
                        (uint32_t)(wn * 32 + np * 16 + d_add) * 2;
                    uint32_t r0, r1, r2, r3;
                    ldsm4t(r0, r1, r2, r3, addr);
                    mma16(acc[0][np * 2 + 0], af[0][0], af[0][1], af[0][2], af[0][3], r0, r1);
                    mma16(acc[1][np * 2 + 0], af[1][0], af[1][1], af[1][2], af[1][3], r0, r1);
                    mma16(acc[0][np * 2 + 1], af[0][0], af[0][1], af[0][2], af[0][3], r2, r3);
                    mma16(acc[1][np * 2 + 1], af[1][0], af[1][1], af[1][2], af[1][3], r2, r3);
                }
            }
            __syncthreads();
            if (s + 2 < 10) LOAD_V16(s + 2, buf, d0);
        }

#pragma unroll
        for (int mt = 0; mt < 2; mt++) {
            const int m0 = wm * 32 + mt * 16 + gid;
#pragma unroll
            for (int nt = 0; nt < 4; nt++) {
                const int col = d0 + wn * 32 + nt * 8 + tig * 2;
                __half2 h0 = __floats2half2_rn(acc[mt][nt][0], acc[mt][nt][1]);
                __half2 h1 = __floats2half2_rn(acc[mt][nt][2], acc[mt][nt][3]);
                *(uint32_t*)(O + (brow + s0 + m0) * DIM + col)     = *(uint32_t*)&h0;
                *(uint32_t*)(O + (brow + s0 + m0 + 8) * DIM + col) = *(uint32_t*)&h1;
            }
        }
    }
}

// ---------------- residual + LayerNorm (fp16 X, fp32 residual, fp16 out) ----------------
__global__ __launch_bounds__(256)
void ln_kernel(const __half* __restrict__ X, const float* __restrict__ R,
               const float* __restrict__ g, const float* __restrict__ bta,
               __half* __restrict__ Yh)
{
    const int r = blockIdx.x, tid = threadIdx.x;
    const size_t base = (size_t)r * DIM;
    uint2 xu = *(const uint2*)(X + base + tid * 4);
    __half2 xh0 = *(__half2*)&xu.x, xh1 = *(__half2*)&xu.y;
    float2 f0 = __half22float2(xh0), f1 = __half22float2(xh1);
    float4 v = make_float4(f0.x, f0.y, f1.x, f1.y);
    float4 rv = *(const float4*)(R + base + tid * 4);
    v.x += rv.x; v.y += rv.y; v.z += rv.z; v.w += rv.w;

    __shared__ float red[8];
    __shared__ float s_mu, s_inv;
    const int w = tid >> 5, lane = tid & 31;

    float s = v.x + v.y + v.z + v.w;
#pragma unroll
    for (int o = 16; o; o >>= 1) s += __shfl_xor_sync(0xffffffffu, s, o);
    if (lane == 0) red[w] = s;
    __syncthreads();
    if (tid == 0) {
        float t = 0.f;
#pragma unroll
        for (int i = 0; i < 8; i++) t += red[i];
        s_mu = t * (1.f / DIM);
    }
    __syncthreads();
    float mu = s_mu;

    float dx = v.x - mu, dy = v.y - mu, dz = v.z - mu, dw = v.w - mu;
    float ss = dx*dx + dy*dy + dz*dz + dw*dw;
#pragma unroll
    for (int o = 16; o; o >>= 1) ss += __shfl_xor_sync(0xffffffffu, ss, o);
    if (lane == 0) red[w] = ss;
    __syncthreads();
    if (tid == 0) {
        float t = 0.f;
#pragma unroll
        for (int i = 0; i < 8; i++) t += red[i];
        s_inv = rsqrtf(t * (1.f / DIM) + 1e-6f);
    }
    __syncthreads();
    float inv = s_inv;

    float4 gg = *(const float4*)(g + tid * 4);
    float4 bb = *(const float4*)(bta + tid * 4);
    float ox = dx * inv * gg.x + bb.x;
    float oy = dy * inv * gg.y + bb.y;
    float oz = dz * inv * gg.z + bb.z;
    float ow = dw * inv * gg.w + bb.w;
    __half2 h0 = __floats2half2_rn(ox, oy);
    __half2 h1 = __floats2half2_rn(oz, ow);
    uint2 u; u.x = *(uint32_t*)&h0; u.y = *(uint32_t*)&h1;
    *(uint2*)(Yh + base + tid * 4) = u;
}

// ---------------- fused LayerNorm + head (fp16 X) ----------------
__global__ __launch_bounds__(256)
void ln_head(const __half* __restrict__ X,
             const float* __restrict__ g, const float* __restrict__ bta,
             const float* __restrict__ w, const float* __restrict__ bias,
             float* __restrict__ out)
{
    const int r = blockIdx.x, tid = threadIdx.x;
    const size_t base = (size_t)r * DIM;
    uint2 xu = *(const uint2*)(X + base + tid * 4);
    __half2 xh0 = *(__half2*)&xu.x, xh1 = *(__half2*)&xu.y;
    float2 f0 = __half22float2(xh0), f1 = __half22float2(xh1);
    float4 v = make_float4(f0.x, f0.y, f1.x, f1.y);

    __shared__ float red[8];
    __shared__ float s_mu, s_inv;
    const int wr = tid >> 5, lane = tid & 31;

    float s = v.x + v.y + v.z + v.w;
#pragma unroll
    for (int o = 16; o; o >>= 1) s += __shfl_xor_sync(0xffffffffu, s, o);
    if (lane == 0) red[wr] = s;
    __syncthreads();
    if (tid == 0) {
        float t = 0.f;
#pragma unroll
        for (int i = 0; i < 8; i++) t += red[i];
        s_mu = t * (1.f / DIM);
    }
    __syncthreads();
    float mu = s_mu;

    float dx = v.x - mu, dy = v.y - mu, dz = v.z - mu, dw = v.w - mu;
    float ss = dx*dx + dy*dy + dz*dz + dw*dw;
#pragma unroll
    for (int o = 16; o; o >>= 1) ss += __shfl_xor_sync(0xffffffffu, ss, o);
    if (lane == 0) red[wr] = ss;
    __syncthreads();
    if (tid == 0) {
        float t = 0.f;
#pragma unroll
        for (int i = 0; i < 8; i++) t += red[i];
        s_inv = rsqrtf(t * (1.f / DIM) + 1e-6f);
    }
    __syncthreads();
    float inv = s_inv;

    float4 gg = *(const float4*)(g + tid * 4);
    float4 bb = *(const float4*)(bta + tid * 4);
    float4 ww = *(const float4*)(w + tid * 4);
    float dot = (dx * inv * gg.x + bb.x) * ww.x
              + (dy * inv * gg.y + bb.y) * ww.y
              + (dz * inv * gg.z + bb.z) * ww.z
              + (dw * inv * gg.w + bb.w) * ww.w;
#pragma unroll
    for (int o = 16; o; o >>= 1) dot += __shfl_xor_sync(0xffffffffu, dot, o);
    if (lane == 0) red[wr] = dot;
    __syncthreads();
    if (tid == 0) {
        float t = 0.f;
#pragma unroll
        for (int i = 0; i < 8; i++) t += red[i];
        t += bias[0];
        out[r] = 1.f / (1.f + expf(-t));
    }
}

// ---------------- launch ----------------
extern "C" void kernel_launch(void* const* d_in, const int* in_sizes, int n_in,
                              void* d_out, int out_size)
{
    const float* x   = (const float*)d_in[0];
    const float* Wq  = (const float*)d_in[1];
    const float* Wk  = (const float*)d_in[2];
    const float* Wv  = (const float*)d_in[3];
    const float* Wo  = (const float*)d_in[4];
    const float* k1w = (const float*)d_in[5];
    const float* k1b = (const float*)d_in[6];
    const float* k2w = (const float*)d_in[7];
    const float* k2b = (const float*)d_in[8];
    const float* lng = (const float*)d_in[9];
    const float* lnb = (const float*)d_in[10];
    float* out = (float*)d_out;

    __half *x16, *q16, *k16, *v16, *a16, *y16, *c16, *h16;
    __half *wq16, *wk16, *wv16, *wo16, *w116;
    cudaGetSymbolAddress((void**)&x16, g_x16);
    cudaGetSymbolAddress((void**)&q16, g_q16);
    cudaGetSymbolAddress((void**)&k16, g_k16);
    cudaGetSymbolAddress((void**)&v16, g_v16);
    cudaGetSymbolAddress((void**)&a16, g_a16);
    cudaGetSymbolAddress((void**)&y16, g_y16);
    cudaGetSymbolAddress((void**)&c16, g_c16);
    cudaGetSymbolAddress((void**)&h16, g_h16);
    cudaGetSymbolAddress((void**)&wq16, g_wq16);
    cudaGetSymbolAddress((void**)&wk16, g_wk16);
    cudaGetSymbolAddress((void**)&wv16, g_wv16);
    cudaGetSymbolAddress((void**)&wo16, g_wo16);
    cudaGetSymbolAddress((void**)&w116, g_w116);

    cudaFuncSetAttribute(attn_tc, cudaFuncAttributeMaxDynamicSharedMemorySize,
                         ATT_SMEM_BYTES);
    cudaFuncSetAttribute(gemm_h, cudaFuncAttributeMaxDynamicSharedMemorySize,
                         GEMM_SMEM);
    cudaFuncSetAttribute(gemm_qkv, cudaFuncAttributeMaxDynamicSharedMemorySize,
                         GEMM_SMEM);

    conv16<<<(MTOT * DIM) / 1024, 256>>>(x, x16);
    conv16w<<<5 * 1024, 256>>>(Wq, Wk, Wv, Wo, k1w,
                               wq16, wk16, wv16, wo16, w116);

    dim3 gg(DIM / 128, MTOT / 128);        // (8, 128)
    dim3 g3(DIM / 128, MTOT / 128, 3);     // fused QKV

    gemm_qkv<<<g3, 256, GEMM_SMEM>>>(x16, wq16, wk16, wv16, q16, k16, v16);

    attn_tc<<<dim3(SEQ / QB, BATCH), 256, ATT_SMEM_BYTES>>>(q16, k16, v16, a16);

    gemm_h<<<gg, 256, GEMM_SMEM>>>(a16, wo16, nullptr, c16, 0);
    ln_kernel<<<MTOT, 256>>>(c16, x, lng, lnb, y16);
    gemm_h<<<gg, 256, GEMM_SMEM>>>(y16, w116, k1b, h16, 1);
    ln_head<<<MTOT, 256>>>(h16, lng, lnb, k2w, k2b, out);
}

// round 14
// speedup vs baseline: 1.0940x; 1.0069x over previous
#include <cuda_runtime.h>
#include <cuda_fp16.h>
#include <math.h>
#include <stdint.h>

#define BATCH 4
#define SEQ   4096
#define DIM   1024
#define MTOT  (BATCH*SEQ)
#define AP    128

// ---------------- scratch (device globals: allowed) ----------------
__device__ __half g_x16[(size_t)MTOT*DIM];
__device__ __half g_q16[(size_t)MTOT*DIM];
__device__ __half g_k16[(size_t)MTOT*DIM];
__device__ __half g_v16[(size_t)MTOT*DIM];
__device__ __half g_a16[(size_t)MTOT*DIM];    // attn out
__device__ __half g_y16[(size_t)MTOT*DIM];    // ln1 out
__device__ __half g_c16[(size_t)MTOT*DIM];    // Wo out
__device__ __half g_h16[(size_t)MTOT*DIM];    // k1 out
__device__ __half g_wq16[DIM*DIM], g_wk16[DIM*DIM], g_wv16[DIM*DIM];
__device__ __half g_wo16[DIM*DIM], g_w116[DIM*DIM];

// =================== PTX helpers ===================
__device__ __forceinline__ uint32_t s2u(const void* p) {
    uint32_t a;
    asm("{ .reg .u64 t; cvta.to.shared.u64 t, %1; cvt.u32.u64 %0, t; }" : "=r"(a) : "l"(p));
    return a;
}
__device__ __forceinline__ void cp16(uint32_t s, const void* g) {
    asm volatile("cp.async.cg.shared.global [%0], [%1], 16;" :: "r"(s), "l"(g));
}
#define CP_COMMIT() asm volatile("cp.async.commit_group;" ::: "memory")
#define CP_WAIT1()  asm volatile("cp.async.wait_group 1;" ::: "memory")
#define CP_WAIT0()  asm volatile("cp.async.wait_group 0;" ::: "memory")

__device__ __forceinline__ void mma16(float* c, uint32_t a0, uint32_t a1, uint32_t a2,
                                      uint32_t a3, uint32_t b0, uint32_t b1) {
    asm volatile(
        "mma.sync.aligned.m16n8k16.row.col.f32.f16.f16.f32 "
        "{%0,%1,%2,%3}, {%4,%5,%6,%7}, {%8,%9}, {%0,%1,%2,%3};"
        : "+f"(c[0]), "+f"(c[1]), "+f"(c[2]), "+f"(c[3])
        : "r"(a0), "r"(a1), "r"(a2), "r"(a3), "r"(b0), "r"(b1));
}
__device__ __forceinline__ void ldsm4(uint32_t& r0, uint32_t& r1, uint32_t& r2,
                                      uint32_t& r3, uint32_t addr) {
    asm volatile("ldmatrix.sync.aligned.m8n8.x4.shared.b16 {%0,%1,%2,%3}, [%4];"
                 : "=r"(r0), "=r"(r1), "=r"(r2), "=r"(r3) : "r"(addr));
}
__device__ __forceinline__ void ldsm2(uint32_t& r0, uint32_t& r1, uint32_t addr) {
    asm volatile("ldmatrix.sync.aligned.m8n8.x2.shared.b16 {%0,%1}, [%2];"
                 : "=r"(r0), "=r"(r1) : "r"(addr));
}
__device__ __forceinline__ void ldsm4t(uint32_t& r0, uint32_t& r1, uint32_t& r2,
                                       uint32_t& r3, uint32_t addr) {
    asm volatile("ldmatrix.sync.aligned.m8n8.x4.trans.shared.b16 {%0,%1,%2,%3}, [%4];"
                 : "=r"(r0), "=r"(r1), "=r"(r2), "=r"(r3) : "r"(addr));
}

// =================== fp32 -> fp16 conversion ===================
__global__ __launch_bounds__(256)
void conv16(const float* __restrict__ in, __half* __restrict__ out) {
    const size_t i = ((size_t)blockIdx.x * 256 + threadIdx.x) * 4;
    float4 v = *(const float4*)(in + i);
    __half2 h0 = __floats2half2_rn(v.x, v.y);
    __half2 h1 = __floats2half2_rn(v.z, v.w);
    uint2 u;
    u.x = *(uint32_t*)&h0; u.y = *(uint32_t*)&h1;
    *(uint2*)(out + i) = u;
}

__global__ __launch_bounds__(256)
void conv16w(const float* __restrict__ w0, const float* __restrict__ w1,
             const float* __restrict__ w2, const float* __restrict__ w3,
             const float* __restrict__ w4,
             __half* __restrict__ o0, __half* __restrict__ o1,
             __half* __restrict__ o2, __half* __restrict__ o3,
             __half* __restrict__ o4)
{
    const int wsel = blockIdx.x >> 10;
    const int blk  = blockIdx.x & 1023;
    const float* in; __half* out;
    switch (wsel) {
        case 0: in = w0; out = o0; break;
        case 1: in = w1; out = o1; break;
        case 2: in = w2; out = o2; break;
        case 3: in = w3; out = o3; break;
        default: in = w4; out = o4; break;
    }
    const size_t i = ((size_t)blk * 256 + threadIdx.x) * 4;
    float4 v = *(const float4*)(in + i);
    __half2 h0 = __floats2half2_rn(v.x, v.y);
    __half2 h1 = __floats2half2_rn(v.z, v.w);
    uint2 u;
    u.x = *(uint32_t*)&h0; u.y = *(uint32_t*)&h1;
    *(uint2*)(out + i) = u;
}

// =================== fp16 mma.sync GEMM (8 warps, 64x32 warp tile, 3-stage) ===================
#define HBK 64
#define HPITCH 72
#define HSTG_BYTES (128 * 144)
#define GSTAGES 3
#define GEMM_SMEM (2 * GSTAGES * HSTG_BYTES)    // 110592
#define HNSTAGE (DIM / HBK)                      // 16

__device__ __forceinline__ void gemm_body(
    const __half* __restrict__ A, const __half* __restrict__ Bw,
    const float* __restrict__ bias, __half* __restrict__ C16, int doRelu,
    char* smc, int bm, int bn)
{
    const uint32_t As_u = s2u(smc);
    const uint32_t Bs_u = As_u + GSTAGES * HSTG_BYTES;

    const int tid  = threadIdx.x;
    const int warp = tid >> 5, lane = tid & 31;
    const int wm = warp >> 2;
    const int wn = warp & 3;
    const int gid = lane >> 2;
    const int tig = lane & 3;

    const int aRow = (lane & 7) + ((lane >> 3) & 1) * 8;
    const int aCol = (lane >> 4) * 8;
    const int bRow = (lane & 7) + (lane >> 4) * 8;
    const int bCol = ((lane >> 3) & 1) * 8;

    float acc[4][4][4];
#pragma unroll
    for (int i = 0; i < 4; i++)
#pragma unroll
        for (int j = 0; j < 4; j++)
#pragma unroll
            for (int k = 0; k < 4; k++) acc[i][j][k] = 0.f;

#define LOADH(stage, buf)                                                        \
    {                                                                            \
        const int k0 = (stage) * HBK;                                            \
        _Pragma("unroll")                                                        \
        for (int l = 0; l < 4; l++) {                                            \
            int slot = tid + l * 256;                                            \
            int row = slot >> 3, c8 = slot & 7;                                  \
            uint32_t so = (uint32_t)(buf) * HSTG_BYTES + row * 144 + c8 * 16;    \
            cp16(As_u + so, A  + (size_t)(bm + row) * DIM + k0 + c8 * 8);        \
            cp16(Bs_u + so, Bw + (size_t)(bn + row) * DIM + k0 + c8 * 8);        \
        }                                                                        \
        CP_COMMIT();                                                             \
    }

    LOADH(0, 0);
    LOADH(1, 1);

    int buf = 0;
    int nbuf = 2;
#pragma unroll 1
    for (int s = 0; s < HNSTAGE; s++) {
        if (s + 1 < HNSTAGE) { CP_WAIT1(); } else { CP_WAIT0(); }
        __syncthreads();
        if (s + 2 < HNSTAGE) LOADH(s + 2, nbuf);

        const uint32_t Ab_u = As_u + (uint32_t)buf * HSTG_BYTES;
        const uint32_t Bb_u = Bs_u + (uint32_t)buf * HSTG_BYTES;

#pragma unroll
        for (int ks = 0; ks < 4; ks++) {
            const int kb0 = ks * 16;
            uint32_t af[4][4], bf[4][2];
#pragma unroll
            for (int mt = 0; mt < 4; mt++) {
                uint32_t addr = Ab_u +
                    (uint32_t)((wm * 64 + mt * 16 + aRow) * HPITCH + kb0 + aCol) * 2;
                ldsm4(af[mt][0], af[mt][1], af[mt][2], af[mt][3], addr);
            }
#pragma unroll
            for (int p = 0; p < 2; p++) {
                uint32_t addr = Bb_u +
                    (uint32_t)((wn * 32 + p * 16 + bRow) * HPITCH + kb0 + bCol) * 2;
                ldsm4(bf[2*p][0], bf[2*p][1], bf[2*p+1][0], bf[2*p+1][1], addr);
            }
#pragma unroll
            for (int mt = 0; mt < 4; mt++)
#pragma unroll
                for (int nt = 0; nt < 4; nt++)
                    mma16(acc[mt][nt], af[mt][0], af[mt][1], af[mt][2], af[mt][3],
                          bf[nt][0], bf[nt][1]);
        }
        buf  = (buf  == GSTAGES - 1) ? 0 : buf + 1;
        nbuf = (nbuf == GSTAGES - 1) ? 0 : nbuf + 1;
    }

#pragma unroll
    for (int mt = 0; mt < 4; mt++) {
#pragma unroll
        for (int nt = 0; nt < 4; nt++) {
            const int col = bn + wn * 32 + nt * 8 + tig * 2;
            float bx = 0.f, by = 0.f;
            if (bias) { bx = bias[col]; by = bias[col + 1]; }
            const int r0 = bm + wm * 64 + mt * 16 + gid;
            float2 v0 = make_float2(acc[mt][nt][0] + bx, acc[mt][nt][1] + by);
            float2 v1 = make_float2(acc[mt][nt][2] + bx, acc[mt][nt][3] + by);
            if (doRelu) {
                v0.x = fmaxf(v0.x, 0.f); v0.y = fmaxf(v0.y, 0.f);
                v1.x = fmaxf(v1.x, 0.f); v1.y = fmaxf(v1.y, 0.f);
            }
            __half2 h0 = __floats2half2_rn(v0.x, v0.y);
            __half2 h1 = __floats2half2_rn(v1.x, v1.y);
            *(uint32_t*)(C16 + (size_t)r0 * DIM + col)       = *(uint32_t*)&h0;
            *(uint32_t*)(C16 + (size_t)(r0 + 8) * DIM + col) = *(uint32_t*)&h1;
        }
    }
}

__global__ __launch_bounds__(256)
void gemm_h(const __half* __restrict__ A, const __half* __restrict__ Bw,
            const float* __restrict__ bias, __half* __restrict__ C16, int doRelu)
{
    extern __shared__ char smc[];
    gemm_body(A, Bw, bias, C16, doRelu, smc, blockIdx.y * 128, blockIdx.x * 128);
}

__global__ __launch_bounds__(256)
void gemm_qkv(const __half* __restrict__ A,
              const __half* __restrict__ W0, const __half* __restrict__ W1,
              const __half* __restrict__ W2,
              __half* __restrict__ C0, __half* __restrict__ C1,
              __half* __restrict__ C2)
{
    extern __shared__ char smc[];
    const __half* Bw; __half* C;
    if (blockIdx.z == 0)      { Bw = W0; C = C0; }
    else if (blockIdx.z == 1) { Bw = W1; C = C1; }
    else                      { Bw = W2; C = C2; }
    gemm_body(A, Bw, nullptr, C, 0, smc, blockIdx.y * 128, blockIdx.x * 128);
}

// =================== tensor-core banded attention (fp16, ldmatrix, 2 CTA/SM) ===================
#define QB    64
#define KW    320
#define KHALF 160
#define PESTR 328
#define VPITCH 136
#define PS_OFF    0
#define PS_BYTES  (QB * PESTR * 2)
#define AQS_OFF   PS_BYTES
#define AQS_STG   (64 * 144)
#define AKS_OFF   (AQS_OFF + 2 * AQS_STG)
#define AKS_STG   (KHALF * 144)
#define AVS_OFF   AQS_OFF
#define AVS_STG   (64 * VPITCH * 2)             // 64-row V stage: 17408 B
#define ATT_SMEM_BYTES (AKS_OFF + 2 * AKS_STG)  // 106496

__global__ __launch_bounds__(256, 2)
void attn_tc(const __half* __restrict__ Q, const __half* __restrict__ Kk,
             const __half* __restrict__ V, __half* __restrict__ O)
{
    extern __shared__ char smc[];
    __half* Ph = (__half*)(smc + PS_OFF);
    const uint32_t smb = s2u(smc);

    const int tid = threadIdx.x;
    const int warp = tid >> 5, lane = tid & 31;
    const int wm = warp >> 2;
    const int wn = warp & 3;
    const int gid = lane >> 2;
    const int tig = lane & 3;
    const int qb = blockIdx.x;
    const int b  = blockIdx.y;
    const int s0 = qb * QB;
    const int ks0 = s0 - AP;
    const size_t brow = (size_t)b * SEQ;
    const float scale = 0.03125f;
    const __half HNEG = __float2half(-60000.f);

    const int aRow = (lane & 7) + ((lane >> 3) & 1) * 8;
    const int aCol = (lane >> 4) * 8;
    const int bRow = (lane & 7) + (lane >> 4) * 8;
    const int bCol = ((lane >> 3) & 1) * 8;
    const int b2Row = (lane & 7);
    const int b2Col = ((lane >> 3) & 1) * 8;

    // ---------- phase 1: scores in two 160-key passes ----------
#define LOAD_QK(stage, buf, nbase)                                                  \
    {                                                                               \
        const int k0 = (stage) * HBK;                                               \
        _Pragma("unroll")                                                           \
        for (int l = 0; l < 2; l++) {                                               \
            int slot = tid + l * 256;                                               \
            int row = slot >> 3, c8 = slot & 7;                                     \
            cp16(smb + AQS_OFF + (buf) * AQS_STG + row * 144 + c8 * 16,             \
                 Q + (brow + s0 + row) * DIM + k0 + c8 * 8);                        \
        }                                                                           \
        _Pragma("unroll")                                                           \
        for (int l = 0; l < 5; l++) {                                               \
            int slot = tid + l * 256;                                               \
            int row = slot >> 3, c8 = slot & 7;                                     \
            int kr = ks0 + (nbase) + row;                                           \
            kr = kr < 0 ? 0 : (kr > SEQ - 1 ? SEQ - 1 : kr);                        \
            cp16(smb + AKS_OFF + (buf) * AKS_STG + row * 144 + c8 * 16,             \
                 Kk + (brow + kr) * DIM + k0 + c8 * 8);                             \
        }                                                                           \
        CP_COMMIT();                                                                \
    }

#pragma unroll 1
    for (int hf = 0; hf < 2; hf++) {
        const int nbase = hf * KHALF;
        float acc[2][5][4];
#pragma unroll
        for (int i = 0; i < 2; i++)
#pragma unroll
            for (int j = 0; j < 5; j++)
#pragma unroll
                for (int k = 0; k < 4; k++) acc[i][j][k] = 0.f;

        LOAD_QK(0, 0, nbase);
        LOAD_QK(1, 1, nbase);

#pragma unroll 1
        for (int s = 0; s < HNSTAGE; s++) {
            const int buf = s & 1;
            if (s + 1 < HNSTAGE) { CP_WAIT1(); } else { CP_WAIT0(); }
            __syncthreads();
            const uint32_t Qb_u = smb + AQS_OFF + (uint32_t)buf * AQS_STG;
            const uint32_t Kb_u = smb + AKS_OFF + (uint32_t)buf * AKS_STG;
#pragma unroll
            for (int ks = 0; ks < 4; ks++) {
                const int kb0 = ks * 16;
                uint32_t af[2][4], bf[5][2];
#pragma unroll
                for (int mt = 0; mt < 2; mt++) {
                    uint32_t addr = Qb_u +
                        (uint32_t)((wm * 32 + mt * 16 + aRow) * HPITCH + kb0 + aCol) * 2;
                    ldsm4(af[mt][0], af[mt][1], af[mt][2], af[mt][3], addr);
                }
#pragma unroll
                for (int p = 0; p < 2; p++) {
                    uint32_t addr = Kb_u +
                        (uint32_t)((wn * 40 + p * 16 + bRow) * HPITCH + kb0 + bCol) * 2;
                    ldsm4(bf[2*p][0], bf[2*p][1], bf[2*p+1][0], bf[2*p+1][1], addr);
                }
                {
                    uint32_t addr = Kb_u +
                        (uint32_t)((wn * 40 + 32 + b2Row) * HPITCH + kb0 + b2Col) * 2;
                    ldsm2(bf[4][0], bf[4][1], addr);
                }
#pragma unroll
                for (int nt = 0; nt < 5; nt++) {
                    mma16(acc[0][nt], af[0][0], af[0][1], af[0][2], af[0][3],
                          bf[nt][0], bf[nt][1]);
                    mma16(acc[1][nt], af[1][0], af[1][1], af[1][2], af[1][3],
                          bf[nt][0], bf[nt][1]);
                }
            }
            __syncthreads();
            if (s + 2 < HNSTAGE) LOAD_QK(s + 2, buf, nbase);
        }

#pragma unroll
        for (int mt = 0; mt < 2; mt++) {
            const int m0 = wm * 32 + mt * 16 + gid;
#pragma unroll
            for (int nt = 0; nt < 5; nt++) {
                const int n0 = nbase + wn * 40 + nt * 8 + tig * 2;
#pragma unroll
                for (int eh = 0; eh < 2; eh++) {
                    const int m = m0 + eh * 8;
                    const int s = s0 + m;
                    __half hv[2];
#pragma unroll
                    for (int e = 0; e < 2; e++) {
                        const int n = n0 + e;
                        const int t = ks0 + n;
                        bool valid = (t >= 0) && (t < SEQ) && (t != s) &&
                                     (t >= s - AP) && (t <= s + AP);
                        hv[e] = valid ? __float2half(acc[mt][nt][eh * 2 + e] * scale)
                                      : HNEG;
                    }
                    *(uint32_t*)&Ph[m * PESTR + n0] = *(uint32_t*)hv;
                }
            }
        }
        __syncthreads();
    }

    // ---------- phase 2: softmax, P fp16 in place ----------
    {
        for (int rr = 0; rr < 8; rr++) {
            const int m = warp * 8 + rr;
            float pv[10];
            float mx = -1e30f;
#pragma unroll
            for (int l = 0; l < 10; l++) {
                pv[l] = __half2float(Ph[m * PESTR + lane + l * 32]);
                mx = fmaxf(mx, pv[l]);
            }
#pragma unroll
            for (int o = 16; o; o >>= 1) mx = fmaxf(mx, __shfl_xor_sync(0xffffffffu, mx, o));
            float ssum = 0.f;
#pragma unroll
            for (int l = 0; l < 10; l++) {
                float p = __expf(pv[l] - mx);
                pv[l] = p;
                ssum += p;
            }
#pragma unroll
            for (int o = 16; o; o >>= 1) ssum += __shfl_xor_sync(0xffffffffu, ssum, o);
            float inv = 1.f / ssum;
#pragma unroll
            for (int l = 0; l < 10; l++)
                Ph[m * PESTR + lane + l * 32] = __float2half(pv[l] * inv);
        }
    }
    __syncthreads();

    // ---------- phase 3: O = P @ V (fp16, 64-row V stages: 5 stages/chunk) ----------
#define LOAD_V16(tstage, buf, d0v)                                                  \
    {                                                                               \
        const int t0 = (tstage) * 64;                                               \
        _Pragma("unroll")                                                           \
        for (int l = 0; l < 4; l++) {                                               \
            int slot = tid + l * 256;                                               \
            int trow = slot >> 4, c = slot & 15;                                    \
            int tr = ks0 + t0 + trow;                                               \
            tr = tr < 0 ? 0 : (tr > SEQ - 1 ? SEQ - 1 : tr);                        \
            cp16(smb + AVS_OFF + (buf) * AVS_STG + trow * (VPITCH * 2) + c * 16,    \
                 V + (brow + tr) * DIM + (d0v) + c * 8);                            \
        }                                                                           \
        CP_COMMIT();                                                                \
    }

    const int lj   = lane >> 3;
    const int lrow = lane & 7;
    const int t_add = (lj & 1) * 8 + lrow;
    const int d_add = (lj >> 1) * 8;

#pragma unroll 1
    for (int nc = 0; nc < 8; nc++) {
        const int d0 = nc * 128;
        float acc[2][4][4];
#pragma unroll
        for (int i = 0; i < 2; i++)
#pragma unroll
            for (int j = 0; j < 4; j++)
#pragma unroll
                for (int k = 0; k < 4; k++) acc[i][j][k] = 0.f;

        LOAD_V16(0, 0, d0);
        LOAD_V16(1, 1, d0);

#pragma unroll 1
        for (int s = 0; s < 5; s++) {
            const int buf = s & 1;
            if (s + 1 < 5) { CP_WAIT1(); } else { CP_WAIT0(); }
            __syncthreads();
            const uint32_t Vb = smb + AVS_OFF + buf * AVS_STG;
#pragma unroll
            for (int ks = 0; ks < 4; ks++) {
                const int tg = s * 64 + ks * 16;
                uint32_t af[2][4];
#pragma unroll
                for (int mt = 0; mt < 2; mt++) {
                    uint32_t addr = smb +
                        (uint32_t)((wm * 32 + mt * 16 + aRow) * PESTR + tg + aCol) * 2;
                    ldsm4(af[mt][0], af[mt][1], af[mt][2], af[mt][3], addr);
                }
#pragma unroll
                for (int np = 0; np < 2; np++) {
                    const uint32_t addr = Vb +
                        (uint32_t)(ks * 16 + t_add) * (VPITCH * 2) +
                        (uint32_t)(wn * 32 + np * 16 + d_add) * 2;
                    uint32_t r0, r1, r2, r3;
                    ldsm4t(r0, r1, r2, r3, addr);
                    mma16(acc[0][np * 2 + 0], af[0][0], af[0][1], af[0][2], af[0][3], r0, r1);
                    mma16(acc[1][np * 2 + 0], af[1][0], af[1][1], af[1][2], af[1][3], r0, r1);
                    mma16(acc[0][np * 2 + 1], af[0][0], af[0][1], af[0][2], af[0][3], r2, r3);
                    mma16(acc[1][np * 2 + 1], af[1][0], af[1][1], af[1][2], af[1][3], r2, r3);
                }
            }
            __syncthreads();
            if (s + 2 < 5) LOAD_V16(s + 2, buf, d0);
        }

#pragma unroll
        for (int mt = 0; mt < 2; mt++) {
            const int m0 = wm * 32 + mt * 16 + gid;
#pragma unroll
            for (int nt = 0; nt < 4; nt++) {
                const int col = d0 + wn * 32 + nt * 8 + tig * 2;
                __half2 h0 = __floats2half2_rn(acc[mt][nt][0], acc[mt][nt][1]);
                __half2 h1 = __floats2half2_rn(acc[mt][nt][2], acc[mt][nt][3]);
                *(uint32_t*)(O + (brow + s0 + m0) * DIM + col)     = *(uint32_t*)&h0;
                *(uint32_t*)(O + (brow + s0 + m0 + 8) * DIM + col) = *(uint32_t*)&h1;
            }
        }
    }
}

// ---------------- residual + LayerNorm (fp16 X, fp16 residual, fp16 out) ----------------
__global__ __launch_bounds__(256)
void ln_kernel(const __half* __restrict__ X, const __half* __restrict__ R,
               const float* __restrict__ g, const float* __restrict__ bta,
               __half* __restrict__ Yh)
{
    const int r = blockIdx.x, tid = threadIdx.x;
    const size_t base = (size_t)r * DIM;
    uint2 xu = *(const uint2*)(X + base + tid * 4);
    __half2 xh0 = *(__half2*)&xu.x, xh1 = *(__half2*)&xu.y;
    float2 f0 = __half22float2(xh0), f1 = __half22float2(xh1);
    float4 v = make_float4(f0.x, f0.y, f1.x, f1.y);
    uint2 ru = *(const uint2*)(R + base + tid * 4);
    __half2 rh0 = *(__half2*)&ru.x, rh1 = *(__half2*)&ru.y;
    float2 r0 = __half22float2(rh0), r1 = __half22float2(rh1);
    v.x += r0.x; v.y += r0.y; v.z += r1.x; v.w += r1.y;

    __shared__ float red[8];
    __shared__ float s_mu, s_inv;
    const int w = tid >> 5, lane = tid & 31;

    float s = v.x + v.y + v.z + v.w;
#pragma unroll
    for (int o = 16; o; o >>= 1) s += __shfl_xor_sync(0xffffffffu, s, o);
    if (lane == 0) red[w] = s;
    __syncthreads();
    if (tid == 0) {
        float t = 0.f;
#pragma unroll
        for (int i = 0; i < 8; i++) t += red[i];
        s_mu = t * (1.f / DIM);
    }
    __syncthreads();
    float mu = s_mu;

    float dx = v.x - mu, dy = v.y - mu, dz = v.z - mu, dw = v.w - mu;
    float ss = dx*dx + dy*dy + dz*dz + dw*dw;
#pragma unroll
    for (int o = 16; o; o >>= 1) ss += __shfl_xor_sync(0xffffffffu, ss, o);
    if (lane == 0) red[w] = ss;
    __syncthreads();
    if (tid == 0) {
        float t = 0.f;
#pragma unroll
        for (int i = 0; i < 8; i++) t += red[i];
        s_inv = rsqrtf(t * (1.f / DIM) + 1e-6f);
    }
    __syncthreads();
    float inv = s_inv;

    float4 gg = *(const float4*)(g + tid * 4);
    float4 bb = *(const float4*)(bta + tid * 4);
    float ox = dx * inv * gg.x + bb.x;
    float oy = dy * inv * gg.y + bb.y;
    float oz = dz * inv * gg.z + bb.z;
    float ow = dw * inv * gg.w + bb.w;
    __half2 h0 = __floats2half2_rn(ox, oy);
    __half2 h1 = __floats2half2_rn(oz, ow);
    uint2 u; u.x = *(uint32_t*)&h0; u.y = *(uint32_t*)&h1;
    *(uint2*)(Yh + base + tid * 4) = u;
}

// ---------------- fused LayerNorm + head (fp16 X) ----------------
__global__ __launch_bounds__(256)
void ln_head(const __half* __restrict__ X,
             const float* __restrict__ g, const float* __restrict__ bta,
             const float* __restrict__ w, const float* __restrict__ bias,
             float* __restrict__ out)
{
    const int r = blockIdx.x, tid = threadIdx.x;
    const size_t base = (size_t)r * DIM;
    uint2 xu = *(const uint2*)(X + base + tid * 4);
    __half2 xh0 = *(__half2*)&xu.x, xh1 = *(__half2*)&xu.y;
    float2 f0 = __half22float2(xh0), f1 = __half22float2(xh1);
    float4 v = make_float4(f0.x, f0.y, f1.x, f1.y);

    __shared__ float red[8];
    __shared__ float s_mu, s_inv;
    const int wr = tid >> 5, lane = tid & 31;

    float s = v.x + v.y + v.z + v.w;
#pragma unroll
    for (int o = 16; o; o >>= 1) s += __shfl_xor_sync(0xffffffffu, s, o);
    if (lane == 0) red[wr] = s;
    __syncthreads();
    if (tid == 0) {
        float t = 0.f;
#pragma unroll
        for (int i = 0; i < 8; i++) t += red[i];
        s_mu = t * (1.f / DIM);
    }
    __syncthreads();
    float mu = s_mu;

    float dx = v.x - mu, dy = v.y - mu, dz = v.z - mu, dw = v.w - mu;
    float ss = dx*dx + dy*dy + dz*dz + dw*dw;
#pragma unroll
    for (int o = 16; o; o >>= 1) ss += __shfl_xor_sync(0xffffffffu, ss, o);
    if (lane == 0) red[wr] = ss;
    __syncthreads();
    if (tid == 0) {
        float t = 0.f;
#pragma unroll
        for (int i = 0; i < 8; i++) t += red[i];
        s_inv = rsqrtf(t * (1.f / DIM) + 1e-6f);
    }
    __syncthreads();
    float inv = s_inv;

    float4 gg = *(const float4*)(g + tid * 4);
    float4 bb = *(const float4*)(bta + tid * 4);
    float4 ww = *(const float4*)(w + tid * 4);
    float dot = (dx * inv * gg.x + bb.x) * ww.x
              + (dy * inv * gg.y + bb.y) * ww.y
              + (dz * inv * gg.z + bb.z) * ww.z
              + (dw * inv * gg.w + bb.w) * ww.w;
#pragma unroll
    for (int o = 16; o; o >>= 1) dot += __shfl_xor_sync(0xffffffffu, dot, o);
    if (lane == 0) red[wr] = dot;
    __syncthreads();
    if (tid == 0) {
        float t = 0.f;
#pragma unroll
        for (int i = 0; i < 8; i++) t += red[i];
        t += bias[0];
        out[r] = 1.f / (1.f + expf(-t));
    }
}

// ---------------- launch ----------------
extern "C" void kernel_launch(void* const* d_in, const int* in_sizes, int n_in,
                              void* d_out, int out_size)
{
    const float* x   = (const float*)d_in[0];
    const float* Wq  = (const float*)d_in[1];
    const float* Wk  = (const float*)d_in[2];
    const float* Wv  = (const float*)d_in[3];
    const float* Wo  = (const float*)d_in[4];
    const float* k1w = (const float*)d_in[5];
    const float* k1b = (const float*)d_in[6];
    const float* k2w = (const float*)d_in[7];
    const float* k2b = (const float*)d_in[8];
    const float* lng = (const float*)d_in[9];
    const float* lnb = (const float*)d_in[10];
    float* out = (float*)d_out;

    __half *x16, *q16, *k16, *v16, *a16, *y16, *c16, *h16;
    __half *wq16, *wk16, *wv16, *wo16, *w116;
    cudaGetSymbolAddress((void**)&x16, g_x16);
    cudaGetSymbolAddress((void**)&q16, g_q16);
    cudaGetSymbolAddress((void**)&k16, g_k16);
    cudaGetSymbolAddress((void**)&v16, g_v16);
    cudaGetSymbolAddress((void**)&a16, g_a16);
    cudaGetSymbolAddress((void**)&y16, g_y16);
    cudaGetSymbolAddress((void**)&c16, g_c16);
    cudaGetSymbolAddress((void**)&h16, g_h16);
    cudaGetSymbolAddress((void**)&wq16, g_wq16);
    cudaGetSymbolAddress((void**)&wk16, g_wk16);
    cudaGetSymbolAddress((void**)&wv16, g_wv16);
    cudaGetSymbolAddress((void**)&wo16, g_wo16);
    cudaGetSymbolAddress((void**)&w116, g_w116);

    cudaFuncSetAttribute(attn_tc, cudaFuncAttributeMaxDynamicSharedMemorySize,
                         ATT_SMEM_BYTES);
    cudaFuncSetAttribute(gemm_h, cudaFuncAttributeMaxDynamicSharedMemorySize,
                         GEMM_SMEM);
    cudaFuncSetAttribute(gemm_qkv, cudaFuncAttributeMaxDynamicSharedMemorySize,
                         GEMM_SMEM);

    conv16<<<(MTOT * DIM) / 1024, 256>>>(x, x16);
    conv16w<<<5 * 1024, 256>>>(Wq, Wk, Wv, Wo, k1w,
                               wq16, wk16, wv16, wo16, w116);

    dim3 gg(DIM / 128, MTOT / 128);        // (8, 128)
    dim3 g3(DIM / 128, MTOT / 128, 3);     // fused QKV

    gemm_qkv<<<g3, 256, GEMM_SMEM>>>(x16, wq16, wk16, wv16, q16, k16, v16);

    attn_tc<<<dim3(SEQ / QB, BATCH), 256, ATT_SMEM_BYTES>>>(q16, k16, v16, a16);

    gemm_h<<<gg, 256, GEMM_SMEM>>>(a16, wo16, nullptr, c16, 0);
    ln_kernel<<<MTOT, 256>>>(c16, x16, lng, lnb, y16);
    gemm_h<<<gg, 256, GEMM_SMEM>>>(y16, w116, k1b, h16, 1);
    ln_head<<<MTOT, 256>>>(h16, lng, lnb, k2w, k2b, out);
}

// round 15
// speedup vs baseline: 1.1062x; 1.0112x over previous
#include <cuda_runtime.h>
#include <cuda_fp16.h>
#include <math.h>
#include <stdint.h>

#define BATCH 4
#define SEQ   4096
#define DIM   1024
#define MTOT  (BATCH*SEQ)
#define AP    128

// ---------------- scratch (device globals: allowed) ----------------
__device__ __half g_x16[(size_t)MTOT*DIM];
__device__ __half g_q16[(size_t)MTOT*DIM];
__device__ __half g_k16[(size_t)MTOT*DIM];
__device__ __half g_v16[(size_t)MTOT*DIM];
__device__ __half g_a16[(size_t)MTOT*DIM];    // attn out
__device__ __half g_y16[(size_t)MTOT*DIM];    // ln1 out
__device__ __half g_c16[(size_t)MTOT*DIM];    // Wo out
__device__ __half g_h16[(size_t)MTOT*DIM];    // k1 out
__device__ __half g_wq16[DIM*DIM], g_wk16[DIM*DIM], g_wv16[DIM*DIM];
__device__ __half g_wo16[DIM*DIM], g_w116[DIM*DIM];

// =================== PTX helpers ===================
__device__ __forceinline__ uint32_t s2u(const void* p) {
    uint32_t a;
    asm("{ .reg .u64 t; cvta.to.shared.u64 t, %1; cvt.u32.u64 %0, t; }" : "=r"(a) : "l"(p));
    return a;
}
__device__ __forceinline__ void cp16(uint32_t s, const void* g) {
    asm volatile("cp.async.cg.shared.global [%0], [%1], 16;" :: "r"(s), "l"(g));
}
#define CP_COMMIT() asm volatile("cp.async.commit_group;" ::: "memory")
#define CP_WAIT1()  asm volatile("cp.async.wait_group 1;" ::: "memory")
#define CP_WAIT0()  asm volatile("cp.async.wait_group 0;" ::: "memory")

__device__ __forceinline__ void mma16(float* c, uint32_t a0, uint32_t a1, uint32_t a2,
                                      uint32_t a3, uint32_t b0, uint32_t b1) {
    asm volatile(
        "mma.sync.aligned.m16n8k16.row.col.f32.f16.f16.f32 "
        "{%0,%1,%2,%3}, {%4,%5,%6,%7}, {%8,%9}, {%0,%1,%2,%3};"
        : "+f"(c[0]), "+f"(c[1]), "+f"(c[2]), "+f"(c[3])
        : "r"(a0), "r"(a1), "r"(a2), "r"(a3), "r"(b0), "r"(b1));
}
__device__ __forceinline__ void ldsm4(uint32_t& r0, uint32_t& r1, uint32_t& r2,
                                      uint32_t& r3, uint32_t addr) {
    asm volatile("ldmatrix.sync.aligned.m8n8.x4.shared.b16 {%0,%1,%2,%3}, [%4];"
                 : "=r"(r0), "=r"(r1), "=r"(r2), "=r"(r3) : "r"(addr));
}
__device__ __forceinline__ void ldsm2(uint32_t& r0, uint32_t& r1, uint32_t addr) {
    asm volatile("ldmatrix.sync.aligned.m8n8.x2.shared.b16 {%0,%1}, [%2];"
                 : "=r"(r0), "=r"(r1) : "r"(addr));
}
__device__ __forceinline__ void ldsm4t(uint32_t& r0, uint32_t& r1, uint32_t& r2,
                                       uint32_t& r3, uint32_t addr) {
    asm volatile("ldmatrix.sync.aligned.m8n8.x4.trans.shared.b16 {%0,%1,%2,%3}, [%4];"
                 : "=r"(r0), "=r"(r1), "=r"(r2), "=r"(r3) : "r"(addr));
}

// =================== fp32 -> fp16 conversion (x + 5 weights, one launch) ===================
__global__ __launch_bounds__(256)
void conv_all(const float* __restrict__ x,
              const float* __restrict__ w0, const float* __restrict__ w1,
              const float* __restrict__ w2, const float* __restrict__ w3,
              const float* __restrict__ w4,
              __half* __restrict__ ox,
              __half* __restrict__ o0, __half* __restrict__ o1,
              __half* __restrict__ o2, __half* __restrict__ o3,
              __half* __restrict__ o4)
{
    const float* in; __half* out; size_t base;
    if (blockIdx.x < 16384) {           // x: 16384 blocks
        in = x; out = ox; base = (size_t)blockIdx.x * 1024;
    } else {
        const int wsel = (blockIdx.x - 16384) >> 10;
        const int blk  = (blockIdx.x - 16384) & 1023;
        switch (wsel) {
            case 0: in = w0; out = o0; break;
            case 1: in = w1; out = o1; break;
            case 2: in = w2; out = o2; break;
            case 3: in = w3; out = o3; break;
            default: in = w4; out = o4; break;
        }
        base = (size_t)blk * 1024;
    }
    const size_t i = base + threadIdx.x * 4;
    float4 v = *(const float4*)(in + i);
    __half2 h0 = __floats2half2_rn(v.x, v.y);
    __half2 h1 = __floats2half2_rn(v.z, v.w);
    uint2 u;
    u.x = *(uint32_t*)&h0; u.y = *(uint32_t*)&h1;
    *(uint2*)(out + i) = u;
}

// =================== fp16 mma.sync GEMM (8 warps, 64x32 warp tile, 3-stage) ===================
#define HBK 64
#define HPITCH 72
#define HSTG_BYTES (128 * 144)
#define GSTAGES 3
#define GEMM_SMEM (2 * GSTAGES * HSTG_BYTES)    // 110592
#define HNSTAGE (DIM / HBK)                      // 16

__device__ __forceinline__ void gemm_body(
    const __half* __restrict__ A, const __half* __restrict__ Bw,
    const float* __restrict__ bias, __half* __restrict__ C16, int doRelu,
    char* smc, int bm, int bn)
{
    const uint32_t As_u = s2u(smc);
    const uint32_t Bs_u = As_u + GSTAGES * HSTG_BYTES;

    const int tid  = threadIdx.x;
    const int warp = tid >> 5, lane = tid & 31;
    const int wm = warp >> 2;
    const int wn = warp & 3;
    const int gid = lane >> 2;
    const int tig = lane & 3;

    const int aRow = (lane & 7) + ((lane >> 3) & 1) * 8;
    const int aCol = (lane >> 4) * 8;
    const int bRow = (lane & 7) + (lane >> 4) * 8;
    const int bCol = ((lane >> 3) & 1) * 8;

    float acc[4][4][4];
#pragma unroll
    for (int i = 0; i < 4; i++)
#pragma unroll
        for (int j = 0; j < 4; j++)
#pragma unroll
            for (int k = 0; k < 4; k++) acc[i][j][k] = 0.f;

#define LOADH(stage, buf)                                                        \
    {                                                                            \
        const int k0 = (stage) * HBK;                                            \
        _Pragma("unroll")                                                        \
        for (int l = 0; l < 4; l++) {                                            \
            int slot = tid + l * 256;                                            \
            int row = slot >> 3, c8 = slot & 7;                                  \
            uint32_t so = (uint32_t)(buf) * HSTG_BYTES + row * 144 + c8 * 16;    \
            cp16(As_u + so, A  + (size_t)(bm + row) * DIM + k0 + c8 * 8);        \
            cp16(Bs_u + so, Bw + (size_t)(bn + row) * DIM + k0 + c8 * 8);        \
        }                                                                        \
        CP_COMMIT();                                                             \
    }

    LOADH(0, 0);
    LOADH(1, 1);

    int buf = 0;
    int nbuf = 2;
#pragma unroll 1
    for (int s = 0; s < HNSTAGE; s++) {
        if (s + 1 < HNSTAGE) { CP_WAIT1(); } else { CP_WAIT0(); }
        __syncthreads();
        if (s + 2 < HNSTAGE) LOADH(s + 2, nbuf);

        const uint32_t Ab_u = As_u + (uint32_t)buf * HSTG_BYTES;
        const uint32_t Bb_u = Bs_u + (uint32_t)buf * HSTG_BYTES;

#pragma unroll
        for (int ks = 0; ks < 4; ks++) {
            const int kb0 = ks * 16;
            uint32_t af[4][4], bf[4][2];
#pragma unroll
            for (int mt = 0; mt < 4; mt++) {
                uint32_t addr = Ab_u +
                    (uint32_t)((wm * 64 + mt * 16 + aRow) * HPITCH + kb0 + aCol) * 2;
                ldsm4(af[mt][0], af[mt][1], af[mt][2], af[mt][3], addr);
            }
#pragma unroll
            for (int p = 0; p < 2; p++) {
                uint32_t addr = Bb_u +
                    (uint32_t)((wn * 32 + p * 16 + bRow) * HPITCH + kb0 + bCol) * 2;
                ldsm4(bf[2*p][0], bf[2*p][1], bf[2*p+1][0], bf[2*p+1][1], addr);
            }
#pragma unroll
            for (int mt = 0; mt < 4; mt++)
#pragma unroll
                for (int nt = 0; nt < 4; nt++)
                    mma16(acc[mt][nt], af[mt][0], af[mt][1], af[mt][2], af[mt][3],
                          bf[nt][0], bf[nt][1]);
        }
        buf  = (buf  == GSTAGES - 1) ? 0 : buf + 1;
        nbuf = (nbuf == GSTAGES - 1) ? 0 : nbuf + 1;
    }

#pragma unroll
    for (int mt = 0; mt < 4; mt++) {
#pragma unroll
        for (int nt = 0; nt < 4; nt++) {
            const int col = bn + wn * 32 + nt * 8 + tig * 2;
            float bx = 0.f, by = 0.f;
            if (bias) { bx = bias[col]; by = bias[col + 1]; }
            const int r0 = bm + wm * 64 + mt * 16 + gid;
            float2 v0 = make_float2(acc[mt][nt][0] + bx, acc[mt][nt][1] + by);
            float2 v1 = make_float2(acc[mt][nt][2] + bx, acc[mt][nt][3] + by);
            if (doRelu) {
                v0.x = fmaxf(v0.x, 0.f); v0.y = fmaxf(v0.y, 0.f);
                v1.x = fmaxf(v1.x, 0.f); v1.y = fmaxf(v1.y, 0.f);
            }
            __half2 h0 = __floats2half2_rn(v0.x, v0.y);
            __half2 h1 = __floats2half2_rn(v1.x, v1.y);
            *(uint32_t*)(C16 + (size_t)r0 * DIM + col)       = *(uint32_t*)&h0;
            *(uint32_t*)(C16 + (size_t)(r0 + 8) * DIM + col) = *(uint32_t*)&h1;
        }
    }
}

__global__ __launch_bounds__(256)
void gemm_h(const __half* __restrict__ A, const __half* __restrict__ Bw,
            const float* __restrict__ bias, __half* __restrict__ C16, int doRelu)
{
    extern __shared__ char smc[];
    gemm_body(A, Bw, bias, C16, doRelu, smc, blockIdx.y * 128, blockIdx.x * 128);
}

__global__ __launch_bounds__(256)
void gemm_qkv(const __half* __restrict__ A,
              const __half* __restrict__ W0, const __half* __restrict__ W1,
              const __half* __restrict__ W2,
              __half* __restrict__ C0, __half* __restrict__ C1,
              __half* __restrict__ C2)
{
    extern __shared__ char smc[];
    const __half* Bw; __half* C;
    if (blockIdx.z == 0)      { Bw = W0; C = C0; }
    else if (blockIdx.z == 1) { Bw = W1; C = C1; }
    else                      { Bw = W2; C = C2; }
    gemm_body(A, Bw, nullptr, C, 0, smc, blockIdx.y * 128, blockIdx.x * 128);
}

// =================== tensor-core banded attention ===================
// Phase 1: SINGLE pass, warp grid 1x8 (warp tile 64x40) over full 320-key window.
// smem: phase1 [Q 2x9216][K 2x46080] = 110592; P (41984) overlays it afterwards.
#define QB    64
#define KW    320
#define PESTR 328
#define VPITCH 136
#define AQS_OFF   0
#define AQS_STG   (64 * 144)                    // 9216
#define AKS_OFF   (2 * AQS_STG)                 // 18432
#define AKS_STG   (KW * 144)                    // 46080
#define PS_OFF    0                             // P overlays Q/K after phase 1
#define PS_BYTES  (QB * PESTR * 2)              // 41984
#define AVS_OFF   PS_BYTES                      // V stages after P
#define AVS_STG   (64 * VPITCH * 2)             // 17408
#define ATT_SMEM_BYTES (AKS_OFF + 2 * AKS_STG)  // 110592

__global__ __launch_bounds__(256, 2)
void attn_tc(const __half* __restrict__ Q, const __half* __restrict__ Kk,
             const __half* __restrict__ V, __half* __restrict__ O)
{
    extern __shared__ char smc[];
    __half* Ph = (__half*)(smc + PS_OFF);
    const uint32_t smb = s2u(smc);

    const int tid = threadIdx.x;
    const int warp = tid >> 5, lane = tid & 31;
    const int gid = lane >> 2;
    const int tig = lane & 3;
    const int qb = blockIdx.x;
    const int b  = blockIdx.y;
    const int s0 = qb * QB;
    const int ks0 = s0 - AP;
    const size_t brow = (size_t)b * SEQ;
    const float scale = 0.03125f;
    const __half HNEG = __float2half(-60000.f);

    const int aRow = (lane & 7) + ((lane >> 3) & 1) * 8;
    const int aCol = (lane >> 4) * 8;
    const int bRow = (lane & 7) + (lane >> 4) * 8;
    const int bCol = ((lane >> 3) & 1) * 8;
    const int b2Row = (lane & 7);
    const int b2Col = ((lane >> 3) & 1) * 8;

    // ---------- phase 1: E[64][320] = Q @ K^T, single pass ----------
#define LOAD_QK(stage, buf)                                                         \
    {                                                                               \
        const int k0 = (stage) * HBK;                                               \
        _Pragma("unroll")                                                           \
        for (int l = 0; l < 2; l++) {                                               \
            int slot = tid + l * 256;                                               \
            int row = slot >> 3, c8 = slot & 7;                                     \
            cp16(smb + AQS_OFF + (buf) * AQS_STG + row * 144 + c8 * 16,             \
                 Q + (brow + s0 + row) * DIM + k0 + c8 * 8);                        \
        }                                                                           \
        _Pragma("unroll")                                                           \
        for (int l = 0; l < 10; l++) {                                              \
            int slot = tid + l * 256;                                               \
            int row = slot >> 3, c8 = slot & 7;                                     \
            int kr = ks0 + row;                                                     \
            kr = kr < 0 ? 0 : (kr > SEQ - 1 ? SEQ - 1 : kr);                        \
            cp16(smb + AKS_OFF + (buf) * AKS_STG + row * 144 + c8 * 16,             \
                 Kk + (brow + kr) * DIM + k0 + c8 * 8);                             \
        }                                                                           \
        CP_COMMIT();                                                                \
    }

    {
        float acc[4][5][4];
#pragma unroll
        for (int i = 0; i < 4; i++)
#pragma unroll
            for (int j = 0; j < 5; j++)
#pragma unroll
                for (int k = 0; k < 4; k++) acc[i][j][k] = 0.f;

        LOAD_QK(0, 0);
        LOAD_QK(1, 1);

#pragma unroll 1
        for (int s = 0; s < HNSTAGE; s++) {
            const int buf = s & 1;
            if (s + 1 < HNSTAGE) { CP_WAIT1(); } else { CP_WAIT0(); }
            __syncthreads();
            const uint32_t Qb_u = smb + AQS_OFF + (uint32_t)buf * AQS_STG;
            const uint32_t Kb_u = smb + AKS_OFF + (uint32_t)buf * AKS_STG;
#pragma unroll
            for (int ks = 0; ks < 4; ks++) {
                const int kb0 = ks * 16;
                uint32_t af[4][4], bf[5][2];
#pragma unroll
                for (int mt = 0; mt < 4; mt++) {
                    uint32_t addr = Qb_u +
                        (uint32_t)((mt * 16 + aRow) * HPITCH + kb0 + aCol) * 2;
                    ldsm4(af[mt][0], af[mt][1], af[mt][2], af[mt][3], addr);
                }
#pragma unroll
                for (int p = 0; p < 2; p++) {
                    uint32_t addr = Kb_u +
                        (uint32_t)((warp * 40 + p * 16 + bRow) * HPITCH + kb0 + bCol) * 2;
                    ldsm4(bf[2*p][0], bf[2*p][1], bf[2*p+1][0], bf[2*p+1][1], addr);
                }
                {
                    uint32_t addr = Kb_u +
                        (uint32_t)((warp * 40 + 32 + b2Row) * HPITCH + kb0 + b2Col) * 2;
                    ldsm2(bf[4][0], bf[4][1], addr);
                }
#pragma unroll
                for (int mt = 0; mt < 4; mt++)
#pragma unroll
                    for (int nt = 0; nt < 5; nt++)
                        mma16(acc[mt][nt], af[mt][0], af[mt][1], af[mt][2], af[mt][3],
                              bf[nt][0], bf[nt][1]);
            }
            __syncthreads();
            if (s + 2 < HNSTAGE) LOAD_QK(s + 2, buf);
        }

        // epilogue: write scores fp16 into P (overlays Q/K region — after last use)
        __syncthreads();
#pragma unroll
        for (int mt = 0; mt < 4; mt++) {
            const int m0 = mt * 16 + gid;
#pragma unroll
            for (int nt = 0; nt < 5; nt++) {
                const int n0 = warp * 40 + nt * 8 + tig * 2;
#pragma unroll
                for (int eh = 0; eh < 2; eh++) {
                    const int m = m0 + eh * 8;
                    const int s = s0 + m;
                    __half hv[2];
#pragma unroll
                    for (int e = 0; e < 2; e++) {
                        const int n = n0 + e;
                        const int t = ks0 + n;
                        bool valid = (t >= 0) && (t < SEQ) && (t != s) &&
                                     (t >= s - AP) && (t <= s + AP);
                        hv[e] = valid ? __float2half(acc[mt][nt][eh * 2 + e] * scale)
                                      : HNEG;
                    }
                    *(uint32_t*)&Ph[m * PESTR + n0] = *(uint32_t*)hv;
                }
            }
        }
    }
    __syncthreads();

    // ---------- phase 2: softmax, P fp16 in place ----------
    {
        for (int rr = 0; rr < 8; rr++) {
            const int m = warp * 8 + rr;
            float pv[10];
            float mx = -1e30f;
#pragma unroll
            for (int l = 0; l < 10; l++) {
                pv[l] = __half2float(Ph[m * PESTR + lane + l * 32]);
                mx = fmaxf(mx, pv[l]);
            }
#pragma unroll
            for (int o = 16; o; o >>= 1) mx = fmaxf(mx, __shfl_xor_sync(0xffffffffu, mx, o));
            float ssum = 0.f;
#pragma unroll
            for (int l = 0; l < 10; l++) {
                float p = __expf(pv[l] - mx);
                pv[l] = p;
                ssum += p;
            }
#pragma unroll
            for (int o = 16; o; o >>= 1) ssum += __shfl_xor_sync(0xffffffffu, ssum, o);
            float inv = 1.f / ssum;
#pragma unroll
            for (int l = 0; l < 10; l++)
                Ph[m * PESTR + lane + l * 32] = __float2half(pv[l] * inv);
        }
    }
    __syncthreads();

    // ---------- phase 3: O = P @ V (fp16, warp grid 2x4, 64-row V stages) ----------
#define LOAD_V16(tstage, buf, d0v)                                                  \
    {                                                                               \
        const int t0 = (tstage) * 64;                                               \
        _Pragma("unroll")                                                           \
        for (int l = 0; l < 4; l++) {                                               \
            int slot = tid + l * 256;                                               \
            int trow = slot >> 4, c = slot & 15;                                    \
            int tr = ks0 + t0 + trow;                                               \
            tr = tr < 0 ? 0 : (tr > SEQ - 1 ? SEQ - 1 : tr);                        \
            cp16(smb + AVS_OFF + (buf) * AVS_STG + trow * (VPITCH * 2) + c * 16,    \
                 V + (brow + tr) * DIM + (d0v) + c * 8);                            \
        }                                                                           \
        CP_COMMIT();                                                                \
    }

    const int wm = warp >> 2;
    const int wn = warp & 3;
    const int lj   = lane >> 3;
    const int lrow = lane & 7;
    const int t_add = (lj & 1) * 8 + lrow;
    const int d_add = (lj >> 1) * 8;

#pragma unroll 1
    for (int nc = 0; nc < 8; nc++) {
        const int d0 = nc * 128;
        float acc[2][4][4];
#pragma unroll
        for (int i = 0; i < 2; i++)
#pragma unroll
            for (int j = 0; j < 4; j++)
#pragma unroll
                for (int k = 0; k < 4; k++) acc[i][j][k] = 0.f;

        LOAD_V16(0, 0, d0);
        LOAD_V16(1, 1, d0);

#pragma unroll 1
        for (int s = 0; s < 5; s++) {
            const int buf = s & 1;
            if (s + 1 < 5) { CP_WAIT1(); } else { CP_WAIT0(); }
            __syncthreads();
            const uint32_t Vb = smb + AVS_OFF + buf * AVS_STG;
#pragma unroll
            for (int ks = 0; ks < 4; ks++) {
                const int tg = s * 64 + ks * 16;
                uint32_t af[2][4];
#pragma unroll
                for (int mt = 0; mt < 2; mt++) {
                    uint32_t addr = smb + PS_OFF +
                        (uint32_t)((wm * 32 + mt * 16 + aRow) * PESTR + tg + aCol) * 2;
                    ldsm4(af[mt][0], af[mt][1], af[mt][2], af[mt][3], addr);
                }
#pragma unroll
                for (int np = 0; np < 2; np++) {
                    const uint32_t addr = Vb +
                        (uint32_t)(ks * 16 + t_add) * (VPITCH * 2) +
                        (uint32_t)(wn * 32 + np * 16 + d_add) * 2;
                    uint32_t r0, r1, r2, r3;
                    ldsm4t(r0, r1, r2, r3, addr);
                    mma16(acc[0][np * 2 + 0], af[0][0], af[0][1], af[0][2], af[0][3], r0, r1);
                    mma16(acc[1][np * 2 + 0], af[1][0], af[1][1], af[1][2], af[1][3], r0, r1);
                    mma16(acc[0][np * 2 + 1], af[0][0], af[0][1], af[0][2], af[0][3], r2, r3);
                    mma16(acc[1][np * 2 + 1], af[1][0], af[1][1], af[1][2], af[1][3], r2, r3);
                }
            }
            __syncthreads();
            if (s + 2 < 5) LOAD_V16(s + 2, buf, d0);
        }

#pragma unroll
        for (int mt = 0; mt < 2; mt++) {
            const int m0 = wm * 32 + mt * 16 + gid;
#pragma unroll
            for (int nt = 0; nt < 4; nt++) {
                const int col = d0 + wn * 32 + nt * 8 + tig * 2;
                __half2 h0 = __floats2half2_rn(acc[mt][nt][0], acc[mt][nt][1]);
                __half2 h1 = __floats2half2_rn(acc[mt][nt][2], acc[mt][nt][3]);
                *(uint32_t*)(O + (brow + s0 + m0) * DIM + col)     = *(uint32_t*)&h0;
                *(uint32_t*)(O + (brow + s0 + m0 + 8) * DIM + col) = *(uint32_t*)&h1;
            }
        }
    }
}

// ---------------- residual + LayerNorm (fp16 X, fp16 residual, fp16 out) ----------------
__global__ __launch_bounds__(256)
void ln_kernel(const __half* __restrict__ X, const __half* __restrict__ R,
               const float* __restrict__ g, const float* __restrict__ bta,
               __half* __restrict__ Yh)
{
    const int r = blockIdx.x, tid = threadIdx.x;
    const size_t base = (size_t)r * DIM;
    uint2 xu = *(const uint2*)(X + base + tid * 4);
    __half2 xh0 = *(__half2*)&xu.x, xh1 = *(__half2*)&xu.y;
    float2 f0 = __half22float2(xh0), f1 = __half22float2(xh1);
    float4 v = make_float4(f0.x, f0.y, f1.x, f1.y);
    uint2 ru = *(const uint2*)(R + base + tid * 4);
    __half2 rh0 = *(__half2*)&ru.x, rh1 = *(__half2*)&ru.y;
    float2 r0 = __half22float2(rh0), r1 = __half22float2(rh1);
    v.x += r0.x; v.y += r0.y; v.z += r1.x; v.w += r1.y;

    __shared__ float red[8];
    __shared__ float s_mu, s_inv;
    const int w = tid >> 5, lane = tid & 31;

    float s = v.x + v.y + v.z + v.w;
#pragma unroll
    for (int o = 16; o; o >>= 1) s += __shfl_xor_sync(0xffffffffu, s, o);
    if (lane == 0) red[w] = s;
    __syncthreads();
    if (tid == 0) {
        float t = 0.f;
#pragma unroll
        for (int i = 0; i < 8; i++) t += red[i];
        s_mu = t * (1.f / DIM);
    }
    __syncthreads();
    float mu = s_mu;

    float dx = v.x - mu, dy = v.y - mu, dz = v.z - mu, dw = v.w - mu;
    float ss = dx*dx + dy*dy + dz*dz + dw*dw;
#pragma unroll
    for (int o = 16; o; o >>= 1) ss += __shfl_xor_sync(0xffffffffu, ss, o);
    if (lane == 0) red[w] = ss;
    __syncthreads();
    if (tid == 0) {
        float t = 0.f;
#pragma unroll
        for (int i = 0; i < 8; i++) t += red[i];
        s_inv = rsqrtf(t * (1.f / DIM) + 1e-6f);
    }
    __syncthreads();
    float inv = s_inv;

    float4 gg = *(const float4*)(g + tid * 4);
    float4 bb = *(const float4*)(bta + tid * 4);
    float ox = dx * inv * gg.x + bb.x;
    float oy = dy * inv * gg.y + bb.y;
    float oz = dz * inv * gg.z + bb.z;
    float ow = dw * inv * gg.w + bb.w;
    __half2 h0 = __floats2half2_rn(ox, oy);
    __half2 h1 = __floats2half2_rn(oz, ow);
    uint2 u; u.x = *(uint32_t*)&h0; u.y = *(uint32_t*)&h1;
    *(uint2*)(Yh + base + tid * 4) = u;
}

// ---------------- fused LayerNorm + head (fp16 X) ----------------
__global__ __launch_bounds__(256)
void ln_head(const __half* __restrict__ X,
             const float* __restrict__ g, const float* __restrict__ bta,
             const float* __restrict__ w, const float* __restrict__ bias,
             float* __restrict__ out)
{
    const int r = blockIdx.x, tid = threadIdx.x;
    const size_t base = (size_t)r * DIM;
    uint2 xu = *(const uint2*)(X + base + tid * 4);
    __half2 xh0 = *(__half2*)&xu.x, xh1 = *(__half2*)&xu.y;
    float2 f0 = __half22float2(xh0), f1 = __half22float2(xh1);
    float4 v = make_float4(f0.x, f0.y, f1.x, f1.y);

    __shared__ float red[8];
    __shared__ float s_mu, s_inv;
    const int wr = tid >> 5, lane = tid & 31;

    float s = v.x + v.y + v.z + v.w;
#pragma unroll
    for (int o = 16; o; o >>= 1) s += __shfl_xor_sync(0xffffffffu, s, o);
    if (lane == 0) red[wr] = s;
    __syncthreads();
    if (tid == 0) {
        float t = 0.f;
#pragma unroll
        for (int i = 0; i < 8; i++) t += red[i];
        s_mu = t * (1.f / DIM);
    }
    __syncthreads();
    float mu = s_mu;

    float dx = v.x - mu, dy = v.y - mu, dz = v.z - mu, dw = v.w - mu;
    float ss = dx*dx + dy*dy + dz*dz + dw*dw;
#pragma unroll
    for (int o = 16; o; o >>= 1) ss += __shfl_xor_sync(0xffffffffu, ss, o);
    if (lane == 0) red[wr] = ss;
    __syncthreads();
    if (tid == 0) {
        float t = 0.f;
#pragma unroll
        for (int i = 0; i < 8; i++) t += red[i];
        s_inv = rsqrtf(t * (1.f / DIM) + 1e-6f);
    }
    __syncthreads();
    float inv = s_inv;

    float4 gg = *(const float4*)(g + tid * 4);
    float4 bb = *(const float4*)(bta + tid * 4);
    float4 ww = *(const float4*)(w + tid * 4);
    float dot = (dx * inv * gg.x + bb.x) * ww.x
              + (dy * inv * gg.y + bb.y) * ww.y
              + (dz * inv * gg.z + bb.z) * ww.z
              + (dw * inv * gg.w + bb.w) * ww.w;
#pragma unroll
    for (int o = 16; o; o >>= 1) dot += __shfl_xor_sync(0xffffffffu, dot, o);
    if (lane == 0) red[wr] = dot;
    __syncthreads();
    if (tid == 0) {
        float t = 0.f;
#pragma unroll
        for (int i = 0; i < 8; i++) t += red[i];
        t += bias[0];
        out[r] = 1.f / (1.f + expf(-t));
    }
}

// ---------------- launch ----------------
extern "C" void kernel_launch(void* const* d_in, const int* in_sizes, int n_in,
                              void* d_out, int out_size)
{
    const float* x   = (const float*)d_in[0];
    const float* Wq  = (const float*)d_in[1];
    const float* Wk  = (const float*)d_in[2];
    const float* Wv  = (const float*)d_in[3];
    const float* Wo  = (const float*)d_in[4];
    const float* k1w = (const float*)d_in[5];
    const float* k1b = (const float*)d_in[6];
    const float* k2w = (const float*)d_in[7];
    const float* k2b = (const float*)d_in[8];
    const float* lng = (const float*)d_in[9];
    const float* lnb = (const float*)d_in[10];
    float* out = (float*)d_out;

    __half *x16, *q16, *k16, *v16, *a16, *y16, *c16, *h16;
    __half *wq16, *wk16, *wv16, *wo16, *w116;
    cudaGetSymbolAddress((void**)&x16, g_x16);
    cudaGetSymbolAddress((void**)&q16, g_q16);
    cudaGetSymbolAddress((void**)&k16, g_k16);
    cudaGetSymbolAddress((void**)&v16, g_v16);
    cudaGetSymbolAddress((void**)&a16, g_a16);
    cudaGetSymbolAddress((void**)&y16, g_y16);
    cudaGetSymbolAddress((void**)&c16, g_c16);
    cudaGetSymbolAddress((void**)&h16, g_h16);
    cudaGetSymbolAddress((void**)&wq16, g_wq16);
    cudaGetSymbolAddress((void**)&wk16, g_wk16);
    cudaGetSymbolAddress((void**)&wv16, g_wv16);
    cudaGetSymbolAddress((void**)&wo16, g_wo16);
    cudaGetSymbolAddress((void**)&w116, g_w116);

    cudaFuncSetAttribute(attn_tc, cudaFuncAttributeMaxDynamicSharedMemorySize,
                         ATT_SMEM_BYTES);
    cudaFuncSetAttribute(gemm_h, cudaFuncAttributeMaxDynamicSharedMemorySize,
                         GEMM_SMEM);
    cudaFuncSetAttribute(gemm_qkv, cudaFuncAttributeMaxDynamicSharedMemorySize,
                         GEMM_SMEM);

    conv_all<<<16384 + 5 * 1024, 256>>>(x, Wq, Wk, Wv, Wo, k1w,
                                        x16, wq16, wk16, wv16, wo16, w116);

    dim3 gg(DIM / 128, MTOT / 128);        // (8, 128)
    dim3 g3(DIM / 128, MTOT / 128, 3);     // fused QKV

    gemm_qkv<<<g3, 256, GEMM_SMEM>>>(x16, wq16, wk16, wv16, q16, k16, v16);

    attn_tc<<<dim3(SEQ / QB, BATCH), 256, ATT_SMEM_BYTES>>>(q16, k16, v16, a16);

    gemm_h<<<gg, 256, GEMM_SMEM>>>(a16, wo16, nullptr, c16, 0);
    ln_kernel<<<MTOT, 256>>>(c16, x16, lng, lnb, y16);
    gemm_h<<<gg, 256, GEMM_SMEM>>>(y16, w116, k1b, h16, 1);
    ln_head<<<MTOT, 256>>>(h16, lng, lnb, k2w, k2b, out);
}

// round 16
// speedup vs baseline: 1.4638x; 1.3233x over previous
#include <cuda_runtime.h>
#include <cuda_fp16.h>
#include <math.h>
#include <stdint.h>

#define BATCH 4
#define SEQ   4096
#define DIM   1024
#define MTOT  (BATCH*SEQ)
#define AP    128

// ---------------- scratch (device globals: allowed) ----------------
__device__ __half g_x16[(size_t)MTOT*DIM];
__device__ __half g_q16[(size_t)MTOT*DIM];     // Q' = x @ (Wk^T Wq)^T
__device__ __half g_v16[(size_t)MTOT*DIM];     // V' = x @ (Wo Wv)^T
__device__ __half g_a16[(size_t)MTOT*DIM];     // attn out == c
__device__ __half g_y16[(size_t)MTOT*DIM];     // ln1 out
__device__ __half g_h16[(size_t)MTOT*DIM];     // k1 out
__device__ __half g_wo16[DIM*DIM], g_w116[DIM*DIM];
__device__ __half g_wqT[DIM*DIM], g_wkT[DIM*DIM], g_wvT[DIM*DIM];
__device__ __half g_wqk[DIM*DIM], g_wvo[DIM*DIM];

// =================== PTX helpers ===================
__device__ __forceinline__ uint32_t s2u(const void* p) {
    uint32_t a;
    asm("{ .reg .u64 t; cvta.to.shared.u64 t, %1; cvt.u32.u64 %0, t; }" : "=r"(a) : "l"(p));
    return a;
}
__device__ __forceinline__ void cp16(uint32_t s, const void* g) {
    asm volatile("cp.async.cg.shared.global [%0], [%1], 16;" :: "r"(s), "l"(g));
}
#define CP_COMMIT() asm volatile("cp.async.commit_group;" ::: "memory")
#define CP_WAIT1()  asm volatile("cp.async.wait_group 1;" ::: "memory")
#define CP_WAIT0()  asm volatile("cp.async.wait_group 0;" ::: "memory")

__device__ __forceinline__ void mma16(float* c, uint32_t a0, uint32_t a1, uint32_t a2,
                                      uint32_t a3, uint32_t b0, uint32_t b1) {
    asm volatile(
        "mma.sync.aligned.m16n8k16.row.col.f32.f16.f16.f32 "
        "{%0,%1,%2,%3}, {%4,%5,%6,%7}, {%8,%9}, {%0,%1,%2,%3};"
        : "+f"(c[0]), "+f"(c[1]), "+f"(c[2]), "+f"(c[3])
        : "r"(a0), "r"(a1), "r"(a2), "r"(a3), "r"(b0), "r"(b1));
}
__device__ __forceinline__ void ldsm4(uint32_t& r0, uint32_t& r1, uint32_t& r2,
                                      uint32_t& r3, uint32_t addr) {
    asm volatile("ldmatrix.sync.aligned.m8n8.x4.shared.b16 {%0,%1,%2,%3}, [%4];"
                 : "=r"(r0), "=r"(r1), "=r"(r2), "=r"(r3) : "r"(addr));
}
__device__ __forceinline__ void ldsm2(uint32_t& r0, uint32_t& r1, uint32_t addr) {
    asm volatile("ldmatrix.sync.aligned.m8n8.x2.shared.b16 {%0,%1}, [%2];"
                 : "=r"(r0), "=r"(r1) : "r"(addr));
}
__device__ __forceinline__ void ldsm4t(uint32_t& r0, uint32_t& r1, uint32_t& r2,
                                       uint32_t& r3, uint32_t addr) {
    asm volatile("ldmatrix.sync.aligned.m8n8.x4.trans.shared.b16 {%0,%1,%2,%3}, [%4];"
                 : "=r"(r0), "=r"(r1), "=r"(r2), "=r"(r3) : "r"(addr));
}

// =================== conversions ===================
// plain: x (16384 blocks) + Wo (1024) + k1w (1024)
__global__ __launch_bounds__(256)
void conv_all(const float* __restrict__ x, const float* __restrict__ wo,
              const float* __restrict__ w1,
              __half* __restrict__ ox, __half* __restrict__ owo,
              __half* __restrict__ ow1)
{
    const float* in; __half* out; size_t base;
    if (blockIdx.x < 16384) {
        in = x; out = ox; base = (size_t)blockIdx.x * 1024;
    } else if (blockIdx.x < 17408) {
        in = wo; out = owo; base = (size_t)(blockIdx.x - 16384) * 1024;
    } else {
        in = w1; out = ow1; base = (size_t)(blockIdx.x - 17408) * 1024;
    }
    const size_t i = base + threadIdx.x * 4;
    float4 v = *(const float4*)(in + i);
    __half2 h0 = __floats2half2_rn(v.x, v.y);
    __half2 h1 = __floats2half2_rn(v.z, v.w);
    uint2 u;
    u.x = *(uint32_t*)&h0; u.y = *(uint32_t*)&h1;
    *(uint2*)(out + i) = u;
}

// transpose+convert: out[c][r] = (half)in[r][c], 32x32 tiles
__global__ __launch_bounds__(256)
void convT(const float* __restrict__ w0, const float* __restrict__ w1,
           const float* __restrict__ w2,
           __half* __restrict__ o0, __half* __restrict__ o1,
           __half* __restrict__ o2)
{
    const float* in; __half* out;
    if (blockIdx.z == 0)      { in = w0; out = o0; }
    else if (blockIdx.z == 1) { in = w1; out = o1; }
    else                      { in = w2; out = o2; }
    __shared__ float t[32][33];
    const int r0 = blockIdx.y * 32, c0 = blockIdx.x * 32;
    const int tx = threadIdx.x, ty = threadIdx.y;   // 32 x 8
#pragma unroll
    for (int k = 0; k < 4; k++)
        t[ty + 8*k][tx] = in[(size_t)(r0 + ty + 8*k) * DIM + c0 + tx];
    __syncthreads();
#pragma unroll
    for (int k = 0; k < 4; k++)
        out[(size_t)(c0 + ty + 8*k) * DIM + r0 + tx] = __float2half(t[tx][ty + 8*k]);
}

// =================== fp16 mma.sync GEMM (8 warps, 64x32 warp tile, 3-stage) ===================
#define HBK 64
#define HPITCH 72
#define HSTG_BYTES (128 * 144)
#define GSTAGES 3
#define GEMM_SMEM (2 * GSTAGES * HSTG_BYTES)    // 110592
#define HNSTAGE (DIM / HBK)                      // 16

__device__ __forceinline__ void gemm_body(
    const __half* __restrict__ A, const __half* __restrict__ Bw,
    const float* __restrict__ bias, __half* __restrict__ C16, int doRelu,
    char* smc, int bm, int bn)
{
    const uint32_t As_u = s2u(smc);
    const uint32_t Bs_u = As_u + GSTAGES * HSTG_BYTES;

    const int tid  = threadIdx.x;
    const int warp = tid >> 5, lane = tid & 31;
    const int wm = warp >> 2;
    const int wn = warp & 3;
    const int gid = lane >> 2;
    const int tig = lane & 3;

    const int aRow = (lane & 7) + ((lane >> 3) & 1) * 8;
    const int aCol = (lane >> 4) * 8;
    const int bRow = (lane & 7) + (lane >> 4) * 8;
    const int bCol = ((lane >> 3) & 1) * 8;

    float acc[4][4][4];
#pragma unroll
    for (int i = 0; i < 4; i++)
#pragma unroll
        for (int j = 0; j < 4; j++)
#pragma unroll
            for (int k = 0; k < 4; k++) acc[i][j][k] = 0.f;

#define LOADH(stage, buf)                                                        \
    {                                                                            \
        const int k0 = (stage) * HBK;                                            \
        _Pragma("unroll")                                                        \
        for (int l = 0; l < 4; l++) {                                            \
            int slot = tid + l * 256;                                            \
            int row = slot >> 3, c8 = slot & 7;                                  \
            uint32_t so = (uint32_t)(buf) * HSTG_BYTES + row * 144 + c8 * 16;    \
            cp16(As_u + so, A  + (size_t)(bm + row) * DIM + k0 + c8 * 8);        \
            cp16(Bs_u + so, Bw + (size_t)(bn + row) * DIM + k0 + c8 * 8);        \
        }                                                                        \
        CP_COMMIT();                                                             \
    }

    LOADH(0, 0);
    LOADH(1, 1);

    int buf = 0;
    int nbuf = 2;
#pragma unroll 1
    for (int s = 0; s < HNSTAGE; s++) {
        if (s + 1 < HNSTAGE) { CP_WAIT1(); } else { CP_WAIT0(); }
        __syncthreads();
        if (s + 2 < HNSTAGE) LOADH(s + 2, nbuf);

        const uint32_t Ab_u = As_u + (uint32_t)buf * HSTG_BYTES;
        const uint32_t Bb_u = Bs_u + (uint32_t)buf * HSTG_BYTES;

#pragma unroll
        for (int ks = 0; ks < 4; ks++) {
            const int kb0 = ks * 16;
            uint32_t af[4][4], bf[4][2];
#pragma unroll
            for (int mt = 0; mt < 4; mt++) {
                uint32_t addr = Ab_u +
                    (uint32_t)((wm * 64 + mt * 16 + aRow) * HPITCH + kb0 + aCol) * 2;
                ldsm4(af[mt][0], af[mt][1], af[mt][2], af[mt][3], addr);
            }
#pragma unroll
            for (int p = 0; p < 2; p++) {
                uint32_t addr = Bb_u +
                    (uint32_t)((wn * 32 + p * 16 + bRow) * HPITCH + kb0 + bCol) * 2;
                ldsm4(bf[2*p][0], bf[2*p][1], bf[2*p+1][0], bf[2*p+1][1], addr);
            }
#pragma unroll
            for (int mt = 0; mt < 4; mt++)
#pragma unroll
                for (int nt = 0; nt < 4; nt++)
                    mma16(acc[mt][nt], af[mt][0], af[mt][1], af[mt][2], af[mt][3],
                          bf[nt][0], bf[nt][1]);
        }
        buf  = (buf  == GSTAGES - 1) ? 0 : buf + 1;
        nbuf = (nbuf == GSTAGES - 1) ? 0 : nbuf + 1;
    }

#pragma unroll
    for (int mt = 0; mt < 4; mt++) {
#pragma unroll
        for (int nt = 0; nt < 4; nt++) {
            const int col = bn + wn * 32 + nt * 8 + tig * 2;
            float bx = 0.f, by = 0.f;
            if (bias) { bx = bias[col]; by = bias[col + 1]; }
            const int r0 = bm + wm * 64 + mt * 16 + gid;
            float2 v0 = make_float2(acc[mt][nt][0] + bx, acc[mt][nt][1] + by);
            float2 v1 = make_float2(acc[mt][nt][2] + bx, acc[mt][nt][3] + by);
            if (doRelu) {
                v0.x = fmaxf(v0.x, 0.f); v0.y = fmaxf(v0.y, 0.f);
                v1.x = fmaxf(v1.x, 0.f); v1.y = fmaxf(v1.y, 0.f);
            }
            __half2 h0 = __floats2half2_rn(v0.x, v0.y);
            __half2 h1 = __floats2half2_rn(v1.x, v1.y);
            *(uint32_t*)(C16 + (size_t)r0 * DIM + col)       = *(uint32_t*)&h0;
            *(uint32_t*)(C16 + (size_t)(r0 + 8) * DIM + col) = *(uint32_t*)&h1;
        }
    }
}

__global__ __launch_bounds__(256)
void gemm_h(const __half* __restrict__ A, const __half* __restrict__ Bw,
            const float* __restrict__ bias, __half* __restrict__ C16, int doRelu)
{
    extern __shared__ char smc[];
    gemm_body(A, Bw, bias, C16, doRelu, smc, blockIdx.y * 128, blockIdx.x * 128);
}

// weight products: z=0: Wqk = gemm_nt(WkT, WqT); z=1: Wvo = gemm_nt(Wo, WvT)
__global__ __launch_bounds__(256)
void gemm_ww(const __half* __restrict__ A0, const __half* __restrict__ B0,
             __half* __restrict__ C0,
             const __half* __restrict__ A1, const __half* __restrict__ B1,
             __half* __restrict__ C1)
{
    extern __shared__ char smc[];
    if (blockIdx.z == 0)
        gemm_body(A0, B0, nullptr, C0, 0, smc, blockIdx.y * 128, blockIdx.x * 128);
    else
        gemm_body(A1, B1, nullptr, C1, 0, smc, blockIdx.y * 128, blockIdx.x * 128);
}

// fused Q'/V' projections (shared A operand)
__global__ __launch_bounds__(256)
void gemm_qv(const __half* __restrict__ A,
             const __half* __restrict__ W0, const __half* __restrict__ W1,
             __half* __restrict__ C0, __half* __restrict__ C1)
{
    extern __shared__ char smc[];
    const __half* Bw; __half* C;
    if (blockIdx.z == 0) { Bw = W0; C = C0; }
    else                 { Bw = W1; C = C1; }
    gemm_body(A, Bw, nullptr, C, 0, smc, blockIdx.y * 128, blockIdx.x * 128);
}

// =================== tensor-core banded attention ===================
#define QB    64
#define KW    320
#define PESTR 328
#define VPITCH 136
#define AQS_OFF   0
#define AQS_STG   (64 * 144)
#define AKS_OFF   (2 * AQS_STG)
#define AKS_STG   (KW * 144)
#define PS_OFF    0
#define PS_BYTES  (QB * PESTR * 2)
#define AVS_OFF   PS_BYTES
#define AVS_STG   (64 * VPITCH * 2)
#define ATT_SMEM_BYTES (AKS_OFF + 2 * AKS_STG)  // 110592

__global__ __launch_bounds__(256, 2)
void attn_tc(const __half* __restrict__ Q, const __half* __restrict__ Kk,
             const __half* __restrict__ V, __half* __restrict__ O)
{
    extern __shared__ char smc[];
    __half* Ph = (__half*)(smc + PS_OFF);
    const uint32_t smb = s2u(smc);

    const int tid = threadIdx.x;
    const int warp = tid >> 5, lane = tid & 31;
    const int gid = lane >> 2;
    const int tig = lane & 3;
    const int qb = blockIdx.x;
    const int b  = blockIdx.y;
    const int s0 = qb * QB;
    const int ks0 = s0 - AP;
    const size_t brow = (size_t)b * SEQ;
    const float scale = 0.03125f;
    const __half HNEG = __float2half(-60000.f);

    const int aRow = (lane & 7) + ((lane >> 3) & 1) * 8;
    const int aCol = (lane >> 4) * 8;
    const int bRow = (lane & 7) + (lane >> 4) * 8;
    const int bCol = ((lane >> 3) & 1) * 8;
    const int b2Row = (lane & 7);
    const int b2Col = ((lane >> 3) & 1) * 8;

#define LOAD_QK(stage, buf)                                                         \
    {                                                                               \
        const int k0 = (stage) * HBK;                                               \
        _Pragma("unroll")                                                           \
        for (int l = 0; l < 2; l++) {                                               \
            int slot = tid + l * 256;                                               \
            int row = slot >> 3, c8 = slot & 7;                                     \
            cp16(smb + AQS_OFF + (buf) * AQS_STG + row * 144 + c8 * 16,             \
                 Q + (brow + s0 + row) * DIM + k0 + c8 * 8);                        \
        }                                                                           \
        _Pragma("unroll")                                                           \
        for (int l = 0; l < 10; l++) {                                              \
            int slot = tid + l * 256;                                               \
            int row = slot >> 3, c8 = slot & 7;                                     \
            int kr = ks0 + row;                                                     \
            kr = kr < 0 ? 0 : (kr > SEQ - 1 ? SEQ - 1 : kr);                        \
            cp16(smb + AKS_OFF + (buf) * AKS_STG + row * 144 + c8 * 16,             \
                 Kk + (brow + kr) * DIM + k0 + c8 * 8);                             \
        }                                                                           \
        CP_COMMIT();                                                                \
    }

    {
        float acc[4][5][4];
#pragma unroll
        for (int i = 0; i < 4; i++)
#pragma unroll
            for (int j = 0; j < 5; j++)
#pragma unroll
                for (int k = 0; k < 4; k++) acc[i][j][k] = 0.f;

        LOAD_QK(0, 0);
        LOAD_QK(1, 1);

#pragma unroll 1
        for (int s = 0; s < HNSTAGE; s++) {
            const int buf = s & 1;
            if (s + 1 < HNSTAGE) { CP_WAIT1(); } else { CP_WAIT0(); }
            __syncthreads();
            const uint32_t Qb_u = smb + AQS_OFF + (uint32_t)buf * AQS_STG;
            const uint32_t Kb_u = smb + AKS_OFF + (uint32_t)buf * AKS_STG;
#pragma unroll
            for (int ks = 0; ks < 4; ks++) {
                const int kb0 = ks * 16;
                uint32_t af[4][4], bf[5][2];
#pragma unroll
                for (int mt = 0; mt < 4; mt++) {
                    uint32_t addr = Qb_u +
                        (uint32_t)((mt * 16 + aRow) * HPITCH + kb0 + aCol) * 2;
                    ldsm4(af[mt][0], af[mt][1], af[mt][2], af[mt][3], addr);
                }
#pragma unroll
                for (int p = 0; p < 2; p++) {
                    uint32_t addr = Kb_u +
                        (uint32_t)((warp * 40 + p * 16 + bRow) * HPITCH + kb0 + bCol) * 2;
                    ldsm4(bf[2*p][0], bf[2*p][1], bf[2*p+1][0], bf[2*p+1][1], addr);
                }
                {
                    uint32_t addr = Kb_u +
                        (uint32_t)((warp * 40 + 32 + b2Row) * HPITCH + kb0 + b2Col) * 2;
                    ldsm2(bf[4][0], bf[4][1], addr);
                }
#pragma unroll
                for (int mt = 0; mt < 4; mt++)
#pragma unroll
                    for (int nt = 0; nt < 5; nt++)
                        mma16(acc[mt][nt], af[mt][0], af[mt][1], af[mt][2], af[mt][3],
                              bf[nt][0], bf[nt][1]);
            }
            __syncthreads();
            if (s + 2 < HNSTAGE) LOAD_QK(s + 2, buf);
        }

        __syncthreads();
#pragma unroll
        for (int mt = 0; mt < 4; mt++) {
            const int m0 = mt * 16 + gid;
#pragma unroll
            for (int nt = 0; nt < 5; nt++) {
                const int n0 = warp * 40 + nt * 8 + tig * 2;
#pragma unroll
                for (int eh = 0; eh < 2; eh++) {
                    const int m = m0 + eh * 8;
                    const int s = s0 + m;
                    __half hv[2];
#pragma unroll
                    for (int e = 0; e < 2; e++) {
                        const int n = n0 + e;
                        const int t = ks0 + n;
                        bool valid = (t >= 0) && (t < SEQ) && (t != s) &&
                                     (t >= s - AP) && (t <= s + AP);
                        hv[e] = valid ? __float2half(acc[mt][nt][eh * 2 + e] * scale)
                                      : HNEG;
                    }
                    *(uint32_t*)&Ph[m * PESTR + n0] = *(uint32_t*)hv;
                }
            }
        }
    }
    __syncthreads();

    // ---------- phase 2: softmax ----------
    {
        for (int rr = 0; rr < 8; rr++) {
            const int m = warp * 8 + rr;
            float pv[10];
            float mx = -1e30f;
#pragma unroll
            for (int l = 0; l < 10; l++) {
                pv[l] = __half2float(Ph[m * PESTR + lane + l * 32]);
                mx = fmaxf(mx, pv[l]);
            }
#pragma unroll
            for (int o = 16; o; o >>= 1) mx = fmaxf(mx, __shfl_xor_sync(0xffffffffu, mx, o));
            float ssum = 0.f;
#pragma unroll
            for (int l = 0; l < 10; l++) {
                float p = __expf(pv[l] - mx);
                pv[l] = p;
                ssum += p;
            }
#pragma unroll
            for (int o = 16; o; o >>= 1) ssum += __shfl_xor_sync(0xffffffffu, ssum, o);
            float inv = 1.f / ssum;
#pragma unroll
            for (int l = 0; l < 10; l++)
                Ph[m * PESTR + lane + l * 32] = __float2half(pv[l] * inv);
        }
    }
    __syncthreads();

    // ---------- phase 3: O = P @ V' ----------
#define LOAD_V16(tstage, buf, d0v)                                                  \
    {                                                                               \
        const int t0 = (tstage) * 64;                                               \
        _Pragma("unroll")                                                           \
        for (int l = 0; l < 4; l++) {                                               \
            int slot = tid + l * 256;                                               \
            int trow = slot >> 4, c = slot & 15;                                    \
            int tr = ks0 + t0 + trow;                                               \
            tr = tr < 0 ? 0 : (tr > SEQ - 1 ? SEQ - 1 : tr);                        \
            cp16(smb + AVS_OFF + (buf) * AVS_STG + trow * (VPITCH * 2) + c * 16,    \
                 V + (brow + tr) * DIM + (d0v) + c * 8);                            \
        }                                                                           \
        CP_COMMIT();                                                                \
    }

    const int wm = warp >> 2;
    const int wn = warp & 3;
    const int lj   = lane >> 3;
    const int lrow = lane & 7;
    const int t_add = (lj & 1) * 8 + lrow;
    const int d_add = (lj >> 1) * 8;

#pragma unroll 1
    for (int nc = 0; nc < 8; nc++) {
        const int d0 = nc * 128;
        float acc[2][4][4];
#pragma unroll
        for (int i = 0; i < 2; i++)
#pragma unroll
            for (int j = 0; j < 4; j++)
#pragma unroll
                for (int k = 0; k < 4; k++) acc[i][j][k] = 0.f;

        LOAD_V16(0, 0, d0);
        LOAD_V16(1, 1, d0);

#pragma unroll 1
        for (int s = 0; s < 5; s++) {
            const int buf = s & 1;
            if (s + 1 < 5) { CP_WAIT1(); } else { CP_WAIT0(); }
            __syncthreads();
            const uint32_t Vb = smb + AVS_OFF + buf * AVS_STG;
#pragma unroll
            for (int ks = 0; ks < 4; ks++) {
                const int tg = s * 64 + ks * 16;
                uint32_t af[2][4];
#pragma unroll
                for (int mt = 0; mt < 2; mt++) {
                    uint32_t addr = smb + PS_OFF +
                        (uint32_t)((wm * 32 + mt * 16 + aRow) * PESTR + tg + aCol) * 2;
                    ldsm4(af[mt][0], af[mt][1], af[mt][2], af[mt][3], addr);
                }
#pragma unroll
                for (int np = 0; np < 2; np++) {
                    const uint32_t addr = Vb +
                        (uint32_t)(ks * 16 + t_add) * (VPITCH * 2) +
                        (uint32_t)(wn * 32 + np * 16 + d_add) * 2;
                    uint32_t r0, r1, r2, r3;
                    ldsm4t(r0, r1, r2, r3, addr);
                    mma16(acc[0][np * 2 + 0], af[0][0], af[0][1], af[0][2], af[0][3], r0, r1);
                    mma16(acc[1][np * 2 + 0], af[1][0], af[1][1], af[1][2], af[1][3], r0, r1);
                    mma16(acc[0][np * 2 + 1], af[0][0], af[0][1], af[0][2], af[0][3], r2, r3);
                    mma16(acc[1][np * 2 + 1], af[1][0], af[1][1], af[1][2], af[1][3], r2, r3);
                }
            }
            __syncthreads();
            if (s + 2 < 5) LOAD_V16(s + 2, buf, d0);
        }

#pragma unroll
        for (int mt = 0; mt < 2; mt++) {
            const int m0 = wm * 32 + mt * 16 + gid;
#pragma unroll
            for (int nt = 0; nt < 4; nt++) {
                const int col = d0 + wn * 32 + nt * 8 + tig * 2;
                __half2 h0 = __floats2half2_rn(acc[mt][nt][0], acc[mt][nt][1]);
                __half2 h1 = __floats2half2_rn(acc[mt][nt][2], acc[mt][nt][3]);
                *(uint32_t*)(O + (brow + s0 + m0) * DIM + col)     = *(uint32_t*)&h0;
                *(uint32_t*)(O + (brow + s0 + m0 + 8) * DIM + col) = *(uint32_t*)&h1;
            }
        }
    }
}

// ---------------- residual + LayerNorm ----------------
__global__ __launch_bounds__(256)
void ln_kernel(const __half* __restrict__ X, const __half* __restrict__ R,
               const float* __restrict__ g, const float* __restrict__ bta,
               __half* __restrict__ Yh)
{
    const int r = blockIdx.x, tid = threadIdx.x;
    const size_t base = (size_t)r * DIM;
    uint2 xu = *(const uint2*)(X + base + tid * 4);
    __half2 xh0 = *(__half2*)&xu.x, xh1 = *(__half2*)&xu.y;
    float2 f0 = __half22float2(xh0), f1 = __half22float2(xh1);
    float4 v = make_float4(f0.x, f0.y, f1.x, f1.y);
    uint2 ru = *(const uint2*)(R + base + tid * 4);
    __half2 rh0 = *(__half2*)&ru.x, rh1 = *(__half2*)&ru.y;
    float2 r0 = __half22float2(rh0), r1 = __half22float2(rh1);
    v.x += r0.x; v.y += r0.y; v.z += r1.x; v.w += r1.y;

    __shared__ float red[8];
    __shared__ float s_mu, s_inv;
    const int w = tid >> 5, lane = tid & 31;

    float s = v.x + v.y + v.z + v.w;
#pragma unroll
    for (int o = 16; o; o >>= 1) s += __shfl_xor_sync(0xffffffffu, s, o);
    if (lane == 0) red[w] = s;
    __syncthreads();
    if (tid == 0) {
        float t = 0.f;
#pragma unroll
        for (int i = 0; i < 8; i++) t += red[i];
        s_mu = t * (1.f / DIM);
    }
    __syncthreads();
    float mu = s_mu;

    float dx = v.x - mu, dy = v.y - mu, dz = v.z - mu, dw = v.w - mu;
    float ss = dx*dx + dy*dy + dz*dz + dw*dw;
#pragma unroll
    for (int o = 16; o; o >>= 1) ss += __shfl_xor_sync(0xffffffffu, ss, o);
    if (lane == 0) red[w] = ss;
    __syncthreads();
    if (tid == 0) {
        float t = 0.f;
#pragma unroll
        for (int i = 0; i < 8; i++) t += red[i];
        s_inv = rsqrtf(t * (1.f / DIM) + 1e-6f);
    }
    __syncthreads();
    float inv = s_inv;

    float4 gg = *(const float4*)(g + tid * 4);
    float4 bb = *(const float4*)(bta + tid * 4);
    float ox = dx * inv * gg.x + bb.x;
    float oy = dy * inv * gg.y + bb.y;
    float oz = dz * inv * gg.z + bb.z;
    float ow = dw * inv * gg.w + bb.w;
    __half2 h0 = __floats2half2_rn(ox, oy);
    __half2 h1 = __floats2half2_rn(oz, ow);
    uint2 u; u.x = *(uint32_t*)&h0; u.y = *(uint32_t*)&h1;
    *(uint2*)(Yh + base + tid * 4) = u;
}

// ---------------- fused LayerNorm + head ----------------
__global__ __launch_bounds__(256)
void ln_head(const __half* __restrict__ X,
             const float* __restrict__ g, const float* __restrict__ bta,
             const float* __restrict__ w, const float* __restrict__ bias,
             float* __restrict__ out)
{
    const int r = blockIdx.x, tid = threadIdx.x;
    const size_t base = (size_t)r * DIM;
    uint2 xu = *(const uint2*)(X + base + tid * 4);
    __half2 xh0 = *(__half2*)&xu.x, xh1 = *(__half2*)&xu.y;
    float2 f0 = __half22float2(xh0), f1 = __half22float2(xh1);
    float4 v = make_float4(f0.x, f0.y, f1.x, f1.y);

    __shared__ float red[8];
    __shared__ float s_mu, s_inv;
    const int wr = tid >> 5, lane = tid & 31;

    float s = v.x + v.y + v.z + v.w;
#pragma unroll
    for (int o = 16; o; o >>= 1) s += __shfl_xor_sync(0xffffffffu, s, o);
    if (lane == 0) red[wr] = s;
    __syncthreads();
    if (tid == 0) {
        float t = 0.f;
#pragma unroll
        for (int i = 0; i < 8; i++) t += red[i];
        s_mu = t * (1.f / DIM);
    }
    __syncthreads();
    float mu = s_mu;

    float dx = v.x - mu, dy = v.y - mu, dz = v.z - mu, dw = v.w - mu;
    float ss = dx*dx + dy*dy + dz*dz + dw*dw;
#pragma unroll
    for (int o = 16; o; o >>= 1) ss += __shfl_xor_sync(0xffffffffu, ss, o);
    if (lane == 0) red[wr] = ss;
    __syncthreads();
    if (tid == 0) {
        float t = 0.f;
#pragma unroll
        for (int i = 0; i < 8; i++) t += red[i];
        s_inv = rsqrtf(t * (1.f / DIM) + 1e-6f);
    }
    __syncthreads();
    float inv = s_inv;

    float4 gg = *(const float4*)(g + tid * 4);
    float4 bb = *(const float4*)(bta + tid * 4);
    float4 ww = *(const float4*)(w + tid * 4);
    float dot = (dx * inv * gg.x + bb.x) * ww.x
              + (dy * inv * gg.y + bb.y) * ww.y
              + (dz * inv * gg.z + bb.z) * ww.z
              + (dw * inv * gg.w + bb.w) * ww.w;
#pragma unroll
    for (int o = 16; o; o >>= 1) dot += __shfl_xor_sync(0xffffffffu, dot, o);
    if (lane == 0) red[wr] = dot;
    __syncthreads();
    if (tid == 0) {
        float t = 0.f;
#pragma unroll
        for (int i = 0; i < 8; i++) t += red[i];
        t += bias[0];
        out[r] = 1.f / (1.f + expf(-t));
    }
}

// ---------------- launch ----------------
extern "C" void kernel_launch(void* const* d_in, const int* in_sizes, int n_in,
                              void* d_out, int out_size)
{
    const float* x   = (const float*)d_in[0];
    const float* Wq  = (const float*)d_in[1];
    const float* Wk  = (const float*)d_in[2];
    const float* Wv  = (const float*)d_in[3];
    const float* Wo  = (const float*)d_in[4];
    const float* k1w = (const float*)d_in[5];
    const float* k1b = (const float*)d_in[6];
    const float* k2w = (const float*)d_in[7];
    const float* k2b = (const float*)d_in[8];
    const float* lng = (const float*)d_in[9];
    const float* lnb = (const float*)d_in[10];
    float* out = (float*)d_out;

    __half *x16, *q16, *v16, *a16, *y16, *h16;
    __half *wo16, *w116, *wqT, *wkT, *wvT, *wqk, *wvo;
    cudaGetSymbolAddress((void**)&x16, g_x16);
    cudaGetSymbolAddress((void**)&q16, g_q16);
    cudaGetSymbolAddress((void**)&v16, g_v16);
    cudaGetSymbolAddress((void**)&a16, g_a16);
    cudaGetSymbolAddress((void**)&y16, g_y16);
    cudaGetSymbolAddress((void**)&h16, g_h16);
    cudaGetSymbolAddress((void**)&wo16, g_wo16);
    cudaGetSymbolAddress((void**)&w116, g_w116);
    cudaGetSymbolAddress((void**)&wqT, g_wqT);
    cudaGetSymbolAddress((void**)&wkT, g_wkT);
    cudaGetSymbolAddress((void**)&wvT, g_wvT);
    cudaGetSymbolAddress((void**)&wqk, g_wqk);
    cudaGetSymbolAddress((void**)&wvo, g_wvo);

    cudaFuncSetAttribute(attn_tc, cudaFuncAttributeMaxDynamicSharedMemorySize,
                         ATT_SMEM_BYTES);
    cudaFuncSetAttribute(gemm_h, cudaFuncAttributeMaxDynamicSharedMemorySize,
                         GEMM_SMEM);
    cudaFuncSetAttribute(gemm_ww, cudaFuncAttributeMaxDynamicSharedMemorySize,
                         GEMM_SMEM);
    cudaFuncSetAttribute(gemm_qv, cudaFuncAttributeMaxDynamicSharedMemorySize,
                         GEMM_SMEM);

    convT<<<dim3(32, 32, 3), dim3(32, 8)>>>(Wq, Wk, Wv, wqT, wkT, wvT);
    conv_all<<<16384 + 2048, 256>>>(x, Wo, k1w, x16, wo16, w116);

    // weight products: Wqk = WkT @ WqT^T = Wk^T Wq ; Wvo = Wo @ WvT^T = Wo Wv
    gemm_ww<<<dim3(8, 8, 2), 256, GEMM_SMEM>>>(wkT, wqT, wqk, wo16, wvT, wvo);

    // Q' = x @ Wqk^T ; V' = x @ Wvo^T
    gemm_qv<<<dim3(8, 128, 2), 256, GEMM_SMEM>>>(x16, wqk, wvo, q16, v16);

    // attention: keys are raw x16; output is c directly
    attn_tc<<<dim3(SEQ / QB, BATCH), 256, ATT_SMEM_BYTES>>>(q16, x16, v16, a16);

    ln_kernel<<<MTOT, 256>>>(a16, x16, lng, lnb, y16);
    gemm_h<<<dim3(8, 128), 256, GEMM_SMEM>>>(y16, w116, k1b, h16, 1);
    ln_head<<<MTOT, 256>>>(h16, lng, lnb, k2w, k2b, out);
}